// round 11
// baseline (speedup 1.0000x reference)
#include <cuda_runtime.h>
#include <cuda_bf16.h>
#include <mma.h>
#include <cstdint>
#include <math.h>

using namespace nvcuda;
typedef __nv_bfloat16 bf16;

#define Tdim 1024
#define CSCALE 0.18033688011112f   /* 0.125 * log2(e) */

// Scratch (allocation-free __device__ globals; NEVER passed from host as args)
__device__ float g_Q[4194304];            // 16MB [bh][t][d] f32
__device__ float g_K[4194304];
__device__ float g_V[4194304];
__device__ bf16 g_P[67108864];            // 128MB [bh][i][j] = E[h,i-j]·k_j (bf16)
__device__ bf16 g_xhi[4194304], g_xlo[4194304];
__device__ bf16 g_Wah[3145728], g_Wal[3145728];
__device__ bf16 g_Wph[1048576], g_Wpl[1048576];
__device__ bf16 g_Yhi[4194304], g_Ylo[4194304];
// pre-split attention operands
__device__ bf16 g_Kbh[4194304], g_Kbl[4194304];   // K hi/lo [bh][t][d]
__device__ bf16 g_Vth[4194304], g_Vtl[4194304];   // V hi/lo TRANSPOSED [bh][d][t]

// ---------------------------------------------------------------------------
__device__ __forceinline__ uint32_t smem_u32(const void* p) {
    uint32_t a;
    asm("{ .reg .u64 t; cvta.to.shared.u64 t, %1; cvt.u32.u64 %0, t; }" : "=r"(a) : "l"(p));
    return a;
}
__device__ __forceinline__ void cp16(uint32_t dst, const void* src) {
    asm volatile("cp.async.cg.shared.global [%0], [%1], 16;" :: "r"(dst), "l"(src) : "memory");
}
__device__ __forceinline__ float ex2f(float x) {
    float r; asm("ex2.approx.ftz.f32 %0, %1;" : "=f"(r) : "f"(x)); return r;
}
__device__ __forceinline__ void mma16816(float* c, uint32_t a0, uint32_t a1, uint32_t a2,
                                         uint32_t a3, uint32_t b0, uint32_t b1) {
    asm volatile("mma.sync.aligned.m16n8k16.row.col.f32.bf16.bf16.f32 "
        "{%0,%1,%2,%3}, {%4,%5,%6,%7}, {%8,%9}, {%0,%1,%2,%3};"
        : "+f"(c[0]), "+f"(c[1]), "+f"(c[2]), "+f"(c[3])
        : "r"(a0), "r"(a1), "r"(a2), "r"(a3), "r"(b0), "r"(b1));
}
__device__ __forceinline__ void split2(float x, float y, uint32_t& hi, uint32_t& lo) {
    bf16 hx = __float2bfloat16(x), hy = __float2bfloat16(y);
    hi = (uint32_t)__bfloat16_as_ushort(hx) | ((uint32_t)__bfloat16_as_ushort(hy) << 16);
    bf16 lx = __float2bfloat16(x - __bfloat162float(hx));
    bf16 ly = __float2bfloat16(y - __bfloat162float(hy));
    lo = (uint32_t)__bfloat16_as_ushort(lx) | ((uint32_t)__bfloat16_as_ushort(ly) << 16);
}

// ---------------------------------------------------------------------------
// prep: bf16 hi/lo split of x; transpose+split weights
// ---------------------------------------------------------------------------
__global__ void __launch_bounds__(256) split_kernel(const float* __restrict__ s, int n)
{
    for (int i = blockIdx.x * blockDim.x + threadIdx.x; i < n; i += gridDim.x * blockDim.x) {
        float x = s[i];
        bf16 h = __float2bfloat16(x);
        g_xhi[i] = h;
        g_xlo[i] = __float2bfloat16(x - __bfloat162float(h));
    }
}

__global__ void __launch_bounds__(256) transpose_split_kernel(
    const float* __restrict__ W, int which, int K, int N)
{
    bf16* Th = (which == 0) ? g_Wah : g_Wph;
    bf16* Tl = (which == 0) ? g_Wal : g_Wpl;
    __shared__ float t[32][33];
    int n0 = blockIdx.x * 32, k0 = blockIdx.y * 32;
    int tx = threadIdx.x & 31, ty = threadIdx.x >> 5;
    #pragma unroll
    for (int i = 0; i < 32; i += 8)
        t[ty + i][tx] = W[(size_t)(k0 + ty + i) * N + n0 + tx];
    __syncthreads();
    #pragma unroll
    for (int i = 0; i < 32; i += 8) {
        float v = t[tx][ty + i];
        bf16 h = __float2bfloat16(v);
        size_t o = (size_t)(n0 + ty + i) * K + k0 + tx;
        Th[o] = h;
        Tl[o] = __float2bfloat16(v - __bfloat162float(h));
    }
}

// Merged K split + V transpose/split (one pass over each input tile).
// grid (16, 64): 64-row tile of K and V for one bh.
__global__ void __launch_bounds__(256) kv_prep_kernel()
{
    __shared__ float ts[64][65];
    const int t0 = blockIdx.x * 64;
    const int bh = blockIdx.y;
    const int tid = threadIdx.x;

    // K: elementwise hi/lo split, coalesced
    {
        const float* Kg = g_K + ((size_t)bh * 1024 + t0) * 64;
        size_t kbase = ((size_t)bh * 1024 + t0) * 64;
        #pragma unroll
        for (int q = 0; q < 4; q++) {
            int idx = tid + q * 256;
            int row = idx >> 4, c4 = (idx & 15) * 4;
            float4 kv = *(const float4*)(Kg + (size_t)row * 64 + c4);
            uint32_t h0, l0, h1, l1;
            split2(kv.x, kv.y, h0, l0);
            split2(kv.z, kv.w, h1, l1);
            size_t o = kbase + (size_t)row * 64 + c4;
            *(uint32_t*)&g_Kbh[o]     = h0;
            *(uint32_t*)&g_Kbh[o + 2] = h1;
            *(uint32_t*)&g_Kbl[o]     = l0;
            *(uint32_t*)&g_Kbl[o + 2] = l1;
        }
    }

    // V: smem transpose then hi/lo split to [bh][d][t]
    const float* Vg = g_V + ((size_t)bh * 1024 + t0) * 64;
    #pragma unroll
    for (int q = 0; q < 4; q++) {
        int idx = tid + q * 256;
        int row = idx >> 4, c4 = (idx & 15) * 4;
        float4 v = *(const float4*)(Vg + (size_t)row * 64 + c4);
        ts[row][c4+0] = v.x; ts[row][c4+1] = v.y; ts[row][c4+2] = v.z; ts[row][c4+3] = v.w;
    }
    __syncthreads();
    #pragma unroll
    for (int q = 0; q < 4; q++) {
        int idx = tid + q * 256;
        int d = idx >> 4, t4 = (idx & 15) * 4;
        float v0 = ts[t4+0][d], v1 = ts[t4+1][d], v2 = ts[t4+2][d], v3 = ts[t4+3][d];
        uint32_t h0, l0, h1, l1;
        split2(v0, v1, h0, l0);
        split2(v2, v3, h1, l1);
        size_t dst = (size_t)bh * 65536 + (size_t)d * 1024 + t0 + t4;
        *(uint32_t*)&g_Vth[dst]     = h0;
        *(uint32_t*)&g_Vth[dst + 2] = h1;
        *(uint32_t*)&g_Vtl[dst]     = l0;
        *(uint32_t*)&g_Vtl[dst + 2] = l1;
    }
}

// ---------------------------------------------------------------------------
// bf16 3-product WMMA GEMM, 2 CTAs/SM. Round-11 change: MMA issue order
// interleaved by ni so consecutive MMAs never target the same accumulator
// (breaks HMMA RAW chains: hh0,hh1,lh0,lh1,hl0,hl1 per mi).
// ---------------------------------------------------------------------------
#define LDH 40
#define MATH_ (128*LDH)
#define MATB (MATH_*2)
#define STGB (4*MATB)
#define SMEM_GEMM (2*STGB)

__device__ __forceinline__ void ld_mat(uint32_t dstbase, const bf16* __restrict__ src,
                                       int r0, int k0, int K, int tid)
{
    #pragma unroll
    for (int j = 0; j < 2; j++) {
        int idx = tid + j * 256;
        int row = idx >> 2, c = idx & 3;
        cp16(dstbase + row * 80 + c * 16, src + (size_t)(r0 + row) * K + k0 + c * 8);
    }
}

#define LOADSTAGE(t_, s_) do {                                         \
    uint32_t b_ = sb + (s_) * STGB;                                    \
    ld_mat(b_,            Ah, m0, (t_) * 32, K, tid);                  \
    ld_mat(b_ +     MATB, Al, m0, (t_) * 32, K, tid);                  \
    ld_mat(b_ + 2 * MATB, Bh, n0, (t_) * 32, K, tid);                  \
    ld_mat(b_ + 3 * MATB, Bl, n0, (t_) * 32, K, tid);                  \
    asm volatile("cp.async.commit_group;" ::: "memory");               \
} while (0)

__global__ void __launch_bounds__(256, 2) gemm_bf16_kernel(
    int sel, const float* __restrict__ bias, float* __restrict__ Cout,
    int K, int mode, int ldc)
{
    extern __shared__ __align__(128) char smraw[];
    bf16* sh = (bf16*)smraw;
    float* Csm = (float*)smraw;
    uint32_t sb = smem_u32(smraw);

    const bf16* Ah = (sel == 0) ? g_xhi : g_Yhi;
    const bf16* Al = (sel == 0) ? g_xlo : g_Ylo;
    const bf16* Bh = (sel == 0) ? g_Wah : g_Wph;
    const bf16* Bl = (sel == 0) ? g_Wal : g_Wpl;

    const int tid = threadIdx.x, wid = tid >> 5;
    const int warp_m = wid & 1, warp_n = wid >> 1;
    const int m0 = blockIdx.y * 128;
    const int n0 = blockIdx.x * 128;
    const int NT = K >> 5;

    wmma::fragment<wmma::accumulator, 16, 16, 16, float> facc[4][2];
    #pragma unroll
    for (int mi = 0; mi < 4; mi++)
        #pragma unroll
        for (int ni = 0; ni < 2; ni++)
            wmma::fill_fragment(facc[mi][ni], 0.0f);

    LOADSTAGE(0, 0);

    for (int t = 0; t < NT; t++) {
        if (t + 1 < NT) {
            LOADSTAGE(t + 1, (t + 1) & 1);
            asm volatile("cp.async.wait_group 1;" ::: "memory");
        } else {
            asm volatile("cp.async.wait_group 0;" ::: "memory");
        }
        __syncthreads();

        const bf16* Ahs = sh + (size_t)(t & 1) * (4 * MATH_);
        const bf16* Als = Ahs + MATH_;
        const bf16* Bhs = Ahs + 2 * MATH_;
        const bf16* Bls = Ahs + 3 * MATH_;

        #pragma unroll
        for (int kt = 0; kt < 32; kt += 16) {
            wmma::fragment<wmma::matrix_b, 16, 16, 16, bf16, wmma::col_major> fbh[2], fbl[2];
            #pragma unroll
            for (int ni = 0; ni < 2; ni++) {
                int nrow = warp_n * 32 + ni * 16;
                wmma::load_matrix_sync(fbh[ni], Bhs + nrow * LDH + kt, LDH);
                wmma::load_matrix_sync(fbl[ni], Bls + nrow * LDH + kt, LDH);
            }
            #pragma unroll
            for (int mi = 0; mi < 4; mi++) {
                wmma::fragment<wmma::matrix_a, 16, 16, 16, bf16, wmma::row_major> fah, fal;
                int mrow = warp_m * 64 + mi * 16;
                wmma::load_matrix_sync(fah, Ahs + mrow * LDH + kt, LDH);
                wmma::load_matrix_sync(fal, Als + mrow * LDH + kt, LDH);
                // interleaved by ni: no two consecutive MMAs share an accumulator
                wmma::mma_sync(facc[mi][0], fah, fbh[0], facc[mi][0]);
                wmma::mma_sync(facc[mi][1], fah, fbh[1], facc[mi][1]);
                wmma::mma_sync(facc[mi][0], fal, fbh[0], facc[mi][0]);
                wmma::mma_sync(facc[mi][1], fal, fbh[1], facc[mi][1]);
                wmma::mma_sync(facc[mi][0], fah, fbl[0], facc[mi][0]);
                wmma::mma_sync(facc[mi][1], fah, fbl[1], facc[mi][1]);
            }
        }
        __syncthreads();
    }

    #pragma unroll
    for (int mi = 0; mi < 4; mi++)
        #pragma unroll
        for (int ni = 0; ni < 2; ni++)
            wmma::store_matrix_sync(
                Csm + (warp_m * 64 + mi * 16) * 132 + warp_n * 32 + ni * 16,
                facc[mi][ni], 132, wmma::mem_row_major);
    __syncthreads();

    for (int e = tid; e < 128 * 128; e += 256) {
        int mr = e >> 7, nc = e & 127;
        int m = m0 + mr, n = n0 + nc;
        float v = Csm[mr * 132 + nc] + bias[n];
        if (mode == 0) {
            int which = n >> 10;
            int cc = n & 1023;
            int h = cc >> 6, d = cc & 63;
            float* dst = (which == 0) ? g_Q : ((which == 1) ? g_K : g_V);
            int bb = m >> 10, tt = m & 1023;
            dst[(size_t)(((bb * 16 + h) << 10) + tt) * 64 + d] = v;
        } else {
            Cout[(size_t)m * ldc + n] = v;
        }
    }
}

// ---------------------------------------------------------------------------
// pos table via wmma 3-product, OUTPUT LAYOUT [bh][i][j], bf16 storage.
// ---------------------------------------------------------------------------
#define POS_SMEM (4*9216 + 64*68*4)

__global__ void __launch_bounds__(256) pos_kernel(const float* __restrict__ rel)
{
    extern __shared__ __align__(16) char smraw[];
    bf16* Kh = (bf16*)(smraw);
    bf16* Kl = (bf16*)(smraw + 9216);
    bf16* Eh = (bf16*)(smraw + 18432);
    bf16* El = (bf16*)(smraw + 27648);
    float* Ssm = (float*)(smraw + 36864);   // [64][68]

    const int j0 = blockIdx.x * 64;
    const int r0 = blockIdx.y * 64;
    if (j0 + r0 >= Tdim) return;
    const int bh = blockIdx.z, h = bh & 15;
    const int tid = threadIdx.x, wid = tid >> 5;
    const int wm = wid & 3, wn = wid >> 2;
    const int lane = tid & 31;

    {
        const size_t kb = ((size_t)bh * Tdim + j0) * 64;
        #pragma unroll
        for (int q = 0; q < 2; q++) {
            int idx = tid + q * 256;
            int row = idx >> 3, ch = (idx & 7) * 8;
            *(uint4*)(Kh + row * 72 + ch) = *(const uint4*)(g_Kbh + kb + row * 64 + ch);
            *(uint4*)(Kl + row * 72 + ch) = *(const uint4*)(g_Kbl + kb + row * 64 + ch);
        }
        const float* Eg = rel + ((size_t)h * Tdim + r0) * 64;
        #pragma unroll
        for (int q = 0; q < 4; q++) {
            int idx = tid + q * 256;
            int row = idx >> 4, c4 = (idx & 15) * 4;
            float4 ev = *(const float4*)(Eg + (size_t)row * 64 + c4);
            float ee[4] = {ev.x, ev.y, ev.z, ev.w};
            #pragma unroll
            for (int c = 0; c < 4; c++) {
                bf16 he = __float2bfloat16(ee[c]);
                Eh[row * 72 + c4 + c] = he;
                El[row * 72 + c4 + c] = __float2bfloat16(ee[c] - __bfloat162float(he));
            }
        }
    }
    __syncthreads();

    wmma::fragment<wmma::accumulator, 16, 16, 16, float> acc[2];
    #pragma unroll
    for (int ni = 0; ni < 2; ni++) wmma::fill_fragment(acc[ni], 0.0f);
    #pragma unroll
    for (int k = 0; k < 4; k++) {
        wmma::fragment<wmma::matrix_a, 16, 16, 16, bf16, wmma::row_major> fah, fal;
        wmma::load_matrix_sync(fah, Kh + (wm * 16) * 72 + k * 16, 72);
        wmma::load_matrix_sync(fal, Kl + (wm * 16) * 72 + k * 16, 72);
        #pragma unroll
        for (int ni = 0; ni < 2; ni++) {
            wmma::fragment<wmma::matrix_b, 16, 16, 16, bf16, wmma::col_major> fbh, fbl;
            wmma::load_matrix_sync(fbh, Eh + (wn * 32 + ni * 16) * 72 + k * 16, 72);
            wmma::load_matrix_sync(fbl, El + (wn * 32 + ni * 16) * 72 + k * 16, 72);
            wmma::mma_sync(acc[ni], fah, fbh, acc[ni]);
            wmma::mma_sync(acc[ni], fah, fbl, acc[ni]);
            wmma::mma_sync(acc[ni], fal, fbh, acc[ni]);
        }
    }
    #pragma unroll
    for (int ni = 0; ni < 2; ni++)
        wmma::store_matrix_sync(Ssm + (wm * 16) * 68 + wn * 32 + ni * 16, acc[ni], 68,
                                wmma::mem_row_major);
    __syncthreads();

    bf16* Pb = g_P + ((size_t)bh << 20);
    for (int il = wid; il < 127; il += 8) {
        int i = j0 + r0 + il;
        if (i >= Tdim) break;
        #pragma unroll
        for (int hf = 0; hf < 2; hf++) {
            int jc = lane + hf * 32;
            int r = il - jc;
            if (r >= 0 && r < 64)
                Pb[(size_t)i * Tdim + j0 + jc] = __float2bfloat16(Ssm[jc * 68 + r]);
        }
    }
}

// ---------------------------------------------------------------------------
// FA2-style flash attention (raw mma), pre-split bf16 operands, cp.async x2.
// Bias now read as bf16 (half traffic).
// ---------------------------------------------------------------------------
#define FLD 72
#define FST_B 36864
#define FL_SMEM (2*FST_B)

#define FLASH_LOAD(jt_, s_) do {                                               \
    size_t kbase_ = ((size_t)bh * 1024 + (size_t)(jt_) * 64) * 64;             \
    size_t vbase_ = (size_t)bh * 65536 + (size_t)(jt_) * 64;                   \
    _Pragma("unroll")                                                          \
    for (int q_ = 0; q_ < 8; q_++) {                                           \
        int idx_ = tid + q_ * 256;                                             \
        int mat_ = idx_ >> 9, rem_ = idx_ & 511;                               \
        int row_ = rem_ >> 3, c_ = rem_ & 7;                                   \
        const bf16* src_;                                                      \
        if (mat_ == 0)      src_ = g_Kbh + kbase_ + row_ * 64 + c_ * 8;        \
        else if (mat_ == 1) src_ = g_Kbl + kbase_ + row_ * 64 + c_ * 8;        \
        else if (mat_ == 2) src_ = g_Vth + vbase_ + (size_t)row_ * 1024 + c_ * 8; \
        else                src_ = g_Vtl + vbase_ + (size_t)row_ * 1024 + c_ * 8; \
        cp16(sb + (s_) * FST_B + mat_ * 9216 + row_ * 144 + c_ * 16, src_);    \
    }                                                                          \
    asm volatile("cp.async.commit_group;" ::: "memory");                       \
} while (0)

__global__ void __launch_bounds__(256) flash_kernel()
{
    extern __shared__ __align__(16) char fsm[];
    uint16_t* SMh = (uint16_t*)fsm;
    uint32_t sb = smem_u32(fsm);

    const int ib = (int)gridDim.x - 1 - (int)blockIdx.x;   // heavy CTAs first
    const int i0 = ib * 128;
    const int bh = blockIdx.y;
    const int b = bh >> 4, h = bh & 15;
    const int tid = threadIdx.x, wid = tid >> 5, lane = tid & 31;
    const int g = lane >> 2, tig = lane & 3;
    const int iW = i0 + wid * 16;
    const int rA = iW + g, rB = rA + 8;

    uint32_t qh[4][4], ql[4][4];
    {
        const float* Qg = g_Q + (size_t)bh * (Tdim * 64);
        #pragma unroll
        for (int kc = 0; kc < 4; kc++) {
            float2 v0 = *(const float2*)(Qg + (size_t)rA * 64 + kc * 16 + 2 * tig);
            float2 v1 = *(const float2*)(Qg + (size_t)rB * 64 + kc * 16 + 2 * tig);
            float2 v2 = *(const float2*)(Qg + (size_t)rA * 64 + kc * 16 + 2 * tig + 8);
            float2 v3 = *(const float2*)(Qg + (size_t)rB * 64 + kc * 16 + 2 * tig + 8);
            split2(v0.x * CSCALE, v0.y * CSCALE, qh[kc][0], ql[kc][0]);
            split2(v1.x * CSCALE, v1.y * CSCALE, qh[kc][1], ql[kc][1]);
            split2(v2.x * CSCALE, v2.y * CSCALE, qh[kc][2], ql[kc][2]);
            split2(v3.x * CSCALE, v3.y * CSCALE, qh[kc][3], ql[kc][3]);
        }
    }

    float o[8][4];
    #pragma unroll
    for (int t = 0; t < 8; t++) { o[t][0] = 0.f; o[t][1] = 0.f; o[t][2] = 0.f; o[t][3] = 0.f; }
    float mA = -1e30f, mB = -1e30f, lA = 0.f, lB = 0.f;

    const bf16* Pb = g_P + ((size_t)bh << 20);
    const int njt = (i0 + 128) >> 6;

    FLASH_LOAD(0, 0);

    for (int jt = 0; jt < njt; jt++) {
        const int j0 = jt << 6;
        if (jt + 1 < njt) {
            FLASH_LOAD(jt + 1, (jt + 1) & 1);
            asm volatile("cp.async.wait_group 1;" ::: "memory");
        } else {
            asm volatile("cp.async.wait_group 0;" ::: "memory");
        }
        __syncthreads();

        if (j0 <= iW + 15) {
            const uint16_t* Khs = SMh + (jt & 1) * (FST_B / 2);
            const uint16_t* Kls = Khs + 4608;
            const uint16_t* Vhs = Khs + 9216;
            const uint16_t* Vls = Khs + 13824;

            float s[8][4];
            #pragma unroll
            for (int t = 0; t < 8; t++) {
                int j = j0 + t * 8 + 2 * tig;
                __nv_bfloat162 b0 = *(const __nv_bfloat162*)(Pb + (size_t)rA * Tdim + j);
                __nv_bfloat162 b1 = *(const __nv_bfloat162*)(Pb + (size_t)rB * Tdim + j);
                s[t][0] = __bfloat162float(b0.x) * CSCALE;
                s[t][1] = __bfloat162float(b0.y) * CSCALE;
                s[t][2] = __bfloat162float(b1.x) * CSCALE;
                s[t][3] = __bfloat162float(b1.y) * CSCALE;
            }
            #pragma unroll
            for (int kc = 0; kc < 4; kc++) {
                #pragma unroll
                for (int t = 0; t < 8; t++) {
                    uint32_t kb0 = *(const uint32_t*)&Khs[(t * 8 + g) * FLD + kc * 16 + 2 * tig];
                    uint32_t kb1 = *(const uint32_t*)&Khs[(t * 8 + g) * FLD + kc * 16 + 2 * tig + 8];
                    uint32_t kl0 = *(const uint32_t*)&Kls[(t * 8 + g) * FLD + kc * 16 + 2 * tig];
                    uint32_t kl1 = *(const uint32_t*)&Kls[(t * 8 + g) * FLD + kc * 16 + 2 * tig + 8];
                    mma16816(s[t], qh[kc][0], qh[kc][1], qh[kc][2], qh[kc][3], kb0, kb1);
                    mma16816(s[t], qh[kc][0], qh[kc][1], qh[kc][2], qh[kc][3], kl0, kl1);
                    mma16816(s[t], ql[kc][0], ql[kc][1], ql[kc][2], ql[kc][3], kb0, kb1);
                }
            }

            if (j0 + 63 > iW) {
                #pragma unroll
                for (int t = 0; t < 8; t++) {
                    int j = j0 + t * 8 + 2 * tig;
                    if (j     > rA) s[t][0] = -3e38f;
                    if (j + 1 > rA) s[t][1] = -3e38f;
                    if (j     > rB) s[t][2] = -3e38f;
                    if (j + 1 > rB) s[t][3] = -3e38f;
                }
            }

            float mxA = -3e38f, mxB = -3e38f;
            #pragma unroll
            for (int t = 0; t < 8; t++) {
                mxA = fmaxf(mxA, fmaxf(s[t][0], s[t][1]));
                mxB = fmaxf(mxB, fmaxf(s[t][2], s[t][3]));
            }
            mxA = fmaxf(mxA, __shfl_xor_sync(0xffffffffu, mxA, 1));
            mxA = fmaxf(mxA, __shfl_xor_sync(0xffffffffu, mxA, 2));
            mxB = fmaxf(mxB, __shfl_xor_sync(0xffffffffu, mxB, 1));
            mxB = fmaxf(mxB, __shfl_xor_sync(0xffffffffu, mxB, 2));
            float nmA = fmaxf(mA, mxA), nmB = fmaxf(mB, mxB);
            float cA = ex2f(mA - nmA), cB = ex2f(mB - nmB);
            mA = nmA; mB = nmB;
            float sumA = 0.f, sumB = 0.f;
            #pragma unroll
            for (int t = 0; t < 8; t++) {
                s[t][0] = ex2f(s[t][0] - nmA); sumA += s[t][0];
                s[t][1] = ex2f(s[t][1] - nmA); sumA += s[t][1];
                s[t][2] = ex2f(s[t][2] - nmB); sumB += s[t][2];
                s[t][3] = ex2f(s[t][3] - nmB); sumB += s[t][3];
            }
            sumA += __shfl_xor_sync(0xffffffffu, sumA, 1);
            sumA += __shfl_xor_sync(0xffffffffu, sumA, 2);
            sumB += __shfl_xor_sync(0xffffffffu, sumB, 1);
            sumB += __shfl_xor_sync(0xffffffffu, sumB, 2);
            lA = lA * cA + sumA; lB = lB * cB + sumB;
            #pragma unroll
            for (int t = 0; t < 8; t++) {
                o[t][0] *= cA; o[t][1] *= cA; o[t][2] *= cB; o[t][3] *= cB;
            }

            #pragma unroll
            for (int kc = 0; kc < 4; kc++) {
                uint32_t ah[4], al[4];
                split2(s[2*kc][0],   s[2*kc][1],   ah[0], al[0]);
                split2(s[2*kc][2],   s[2*kc][3],   ah[1], al[1]);
                split2(s[2*kc+1][0], s[2*kc+1][1], ah[2], al[2]);
                split2(s[2*kc+1][2], s[2*kc+1][3], ah[3], al[3]);
                #pragma unroll
                for (int t = 0; t < 8; t++) {
                    uint32_t vb0 = *(const uint32_t*)&Vhs[(t * 8 + g) * FLD + kc * 16 + 2 * tig];
                    uint32_t vb1 = *(const uint32_t*)&Vhs[(t * 8 + g) * FLD + kc * 16 + 2 * tig + 8];
                    uint32_t vl0 = *(const uint32_t*)&Vls[(t * 8 + g) * FLD + kc * 16 + 2 * tig];
                    uint32_t vl1 = *(const uint32_t*)&Vls[(t * 8 + g) * FLD + kc * 16 + 2 * tig + 8];
                    mma16816(o[t], ah[0], ah[1], ah[2], ah[3], vb0, vb1);
                    mma16816(o[t], ah[0], ah[1], ah[2], ah[3], vl0, vl1);
                    mma16816(o[t], al[0], al[1], al[2], al[3], vb0, vb1);
                }
            }
        }
        __syncthreads();
    }

    float iA = 1.f / lA, iB = 1.f / lB;
    size_t baseA = ((size_t)(b * Tdim + rA)) * 1024 + h * 64;
    size_t baseB = ((size_t)(b * Tdim + rB)) * 1024 + h * 64;
    #pragma unroll
    for (int t = 0; t < 8; t++) {
        int d = t * 8 + 2 * tig;
        uint32_t hi, lo;
        split2(o[t][0] * iA, o[t][1] * iA, hi, lo);
        *(uint32_t*)&g_Yhi[baseA + d] = hi;
        *(uint32_t*)&g_Ylo[baseA + d] = lo;
        split2(o[t][2] * iB, o[t][3] * iB, hi, lo);
        *(uint32_t*)&g_Yhi[baseB + d] = hi;
        *(uint32_t*)&g_Ylo[baseB + d] = lo;
    }
}

// ---------------------------------------------------------------------------
extern "C" void kernel_launch(void* const* d_in, const int* in_sizes, int n_in,
                              void* d_out, int out_size)
{
    const float* x      = (const float*)d_in[0];
    const float* W_attn = (const float*)d_in[1];
    const float* b_attn = (const float*)d_in[2];
    const float* W_proj = (const float*)d_in[3];
    const float* b_proj = (const float*)d_in[4];
    const float* rel    = (const float*)d_in[5];
    float* out = (float*)d_out;

    cudaFuncSetAttribute(gemm_bf16_kernel,
                         cudaFuncAttributeMaxDynamicSharedMemorySize, SMEM_GEMM);
    cudaFuncSetAttribute(pos_kernel,
                         cudaFuncAttributeMaxDynamicSharedMemorySize, POS_SMEM);
    cudaFuncSetAttribute(flash_kernel,
                         cudaFuncAttributeMaxDynamicSharedMemorySize, FL_SMEM);

    // prep
    split_kernel<<<2048, 256>>>(x, 4096 * 1024);
    transpose_split_kernel<<<dim3(3072/32, 1024/32), 256>>>(W_attn, 0, 1024, 3072);
    transpose_split_kernel<<<dim3(1024/32, 1024/32), 256>>>(W_proj, 1, 1024, 1024);

    // 1) QKV (wmma x3) -> f32 Q/K/V scatter
    gemm_bf16_kernel<<<dim3(24, 32), 256, SMEM_GEMM>>>(0, b_attn, nullptr, 1024, 0, 0);

    // 1b) pre-split K (hi/lo) and V (hi/lo transposed) for flash — merged
    kv_prep_kernel<<<dim3(16, 64), 256>>>();

    // 2) relative-position table (wmma x3), [bh][i][j] layout, bf16
    pos_kernel<<<dim3(16, 16, 64), 256, POS_SMEM>>>(rel);

    // 3) FA2 raw-mma flash with cp.async double buffering -> Yhi/Ylo
    flash_kernel<<<dim3(8, 64), 256, FL_SMEM>>>();

    // 4) out = Y @ W_proj + b_proj (wmma x3)
    gemm_bf16_kernel<<<dim3(8, 32), 256, SMEM_GEMM>>>(1, b_proj, out, 1024, 1, 1024);
}

// round 12
// speedup vs baseline: 1.0259x; 1.0259x over previous
#include <cuda_runtime.h>
#include <cuda_bf16.h>
#include <mma.h>
#include <cstdint>
#include <math.h>

using namespace nvcuda;
typedef __nv_bfloat16 bf16;

#define Tdim 1024
#define CSCALE 0.18033688011112f   /* 0.125 * log2(e) */

// Scratch (allocation-free __device__ globals; NEVER passed from host as args)
__device__ float g_Q[4194304];            // 16MB [bh][t][d] f32
__device__ float g_V[4194304];            // V f32 (transposed+split by v_prep)
__device__ bf16 g_P[67108864];            // 128MB [bh][i][j] bf16
__device__ bf16 g_xhi[4194304], g_xlo[4194304];
__device__ bf16 g_Wah[3145728], g_Wal[3145728];
__device__ bf16 g_Wph[1048576], g_Wpl[1048576];
__device__ bf16 g_Yhi[4194304], g_Ylo[4194304];
__device__ bf16 g_Eh[1048576], g_El[1048576];     // rel pre-split [h][r][d]
// pre-split attention operands
__device__ bf16 g_Kbh[4194304], g_Kbl[4194304];   // K hi/lo [bh][t][d] (from GEMM epilogue)
__device__ bf16 g_Vth[4194304], g_Vtl[4194304];   // V hi/lo TRANSPOSED [bh][d][t]

// ---------------------------------------------------------------------------
__device__ __forceinline__ uint32_t smem_u32(const void* p) {
    uint32_t a;
    asm("{ .reg .u64 t; cvta.to.shared.u64 t, %1; cvt.u32.u64 %0, t; }" : "=r"(a) : "l"(p));
    return a;
}
__device__ __forceinline__ void cp16(uint32_t dst, const void* src) {
    asm volatile("cp.async.cg.shared.global [%0], [%1], 16;" :: "r"(dst), "l"(src) : "memory");
}
__device__ __forceinline__ float ex2f(float x) {
    float r; asm("ex2.approx.ftz.f32 %0, %1;" : "=f"(r) : "f"(x)); return r;
}
__device__ __forceinline__ void mma16816(float* c, uint32_t a0, uint32_t a1, uint32_t a2,
                                         uint32_t a3, uint32_t b0, uint32_t b1) {
    asm volatile("mma.sync.aligned.m16n8k16.row.col.f32.bf16.bf16.f32 "
        "{%0,%1,%2,%3}, {%4,%5,%6,%7}, {%8,%9}, {%0,%1,%2,%3};"
        : "+f"(c[0]), "+f"(c[1]), "+f"(c[2]), "+f"(c[3])
        : "r"(a0), "r"(a1), "r"(a2), "r"(a3), "r"(b0), "r"(b1));
}
__device__ __forceinline__ void split2(float x, float y, uint32_t& hi, uint32_t& lo) {
    bf16 hx = __float2bfloat16(x), hy = __float2bfloat16(y);
    hi = (uint32_t)__bfloat16_as_ushort(hx) | ((uint32_t)__bfloat16_as_ushort(hy) << 16);
    bf16 lx = __float2bfloat16(x - __bfloat162float(hx));
    bf16 ly = __float2bfloat16(y - __bfloat162float(hy));
    lo = (uint32_t)__bfloat16_as_ushort(lx) | ((uint32_t)__bfloat16_as_ushort(ly) << 16);
}

// ---------------------------------------------------------------------------
// prep kernels
// ---------------------------------------------------------------------------
__global__ void __launch_bounds__(256) split_kernel(const float* __restrict__ s, int n)
{
    for (int i = blockIdx.x * blockDim.x + threadIdx.x; i < n; i += gridDim.x * blockDim.x) {
        float x = s[i];
        bf16 h = __float2bfloat16(x);
        g_xhi[i] = h;
        g_xlo[i] = __float2bfloat16(x - __bfloat162float(h));
    }
}

// rel pre-split: f32 -> bf16 hi/lo (one pass; removes 16x redundant convert in pos)
__global__ void __launch_bounds__(256) rel_split_kernel(const float* __restrict__ rel)
{
    for (int i = blockIdx.x * blockDim.x + threadIdx.x; i < 1048576; i += gridDim.x * blockDim.x) {
        float x = rel[i];
        bf16 h = __float2bfloat16(x);
        g_Eh[i] = h;
        g_El[i] = __float2bfloat16(x - __bfloat162float(h));
    }
}

__global__ void __launch_bounds__(256) transpose_split_kernel(
    const float* __restrict__ W, int which, int K, int N)
{
    bf16* Th = (which == 0) ? g_Wah : g_Wph;
    bf16* Tl = (which == 0) ? g_Wal : g_Wpl;
    __shared__ float t[32][33];
    int n0 = blockIdx.x * 32, k0 = blockIdx.y * 32;
    int tx = threadIdx.x & 31, ty = threadIdx.x >> 5;
    #pragma unroll
    for (int i = 0; i < 32; i += 8)
        t[ty + i][tx] = W[(size_t)(k0 + ty + i) * N + n0 + tx];
    __syncthreads();
    #pragma unroll
    for (int i = 0; i < 32; i += 8) {
        float v = t[tx][ty + i];
        bf16 h = __float2bfloat16(v);
        size_t o = (size_t)(n0 + ty + i) * K + k0 + tx;
        Th[o] = h;
        Tl[o] = __float2bfloat16(v - __bfloat162float(h));
    }
}

// V only: f32 [bh][t][d] -> bf16 hi/lo TRANSPOSED [bh][d][t]
__global__ void __launch_bounds__(256) v_prep_kernel()
{
    __shared__ float ts[64][65];
    const int t0 = blockIdx.x * 64;
    const int bh = blockIdx.y;
    const int tid = threadIdx.x;
    const float* Vg = g_V + ((size_t)bh * 1024 + t0) * 64;
    #pragma unroll
    for (int q = 0; q < 4; q++) {
        int idx = tid + q * 256;
        int row = idx >> 4, c4 = (idx & 15) * 4;
        float4 v = *(const float4*)(Vg + (size_t)row * 64 + c4);
        ts[row][c4+0] = v.x; ts[row][c4+1] = v.y; ts[row][c4+2] = v.z; ts[row][c4+3] = v.w;
    }
    __syncthreads();
    #pragma unroll
    for (int q = 0; q < 4; q++) {
        int idx = tid + q * 256;
        int d = idx >> 4, t4 = (idx & 15) * 4;
        float v0 = ts[t4+0][d], v1 = ts[t4+1][d], v2 = ts[t4+2][d], v3 = ts[t4+3][d];
        uint32_t h0, l0, h1, l1;
        split2(v0, v1, h0, l0);
        split2(v2, v3, h1, l1);
        size_t dst = (size_t)bh * 65536 + (size_t)d * 1024 + t0 + t4;
        *(uint32_t*)&g_Vth[dst]     = h0;
        *(uint32_t*)&g_Vth[dst + 2] = h1;
        *(uint32_t*)&g_Vtl[dst]     = l0;
        *(uint32_t*)&g_Vtl[dst + 2] = l1;
    }
}

// ---------------------------------------------------------------------------
// bf16 3-product WMMA GEMM, 2 CTAs/SM — mainloop is the EXACT round-10
// configuration (measured 274us). Epilogue change only: K written directly
// as bf16 hi/lo (no f32 round-trip).
// ---------------------------------------------------------------------------
#define LDH 40
#define MATH_ (128*LDH)
#define MATB (MATH_*2)
#define STGB (4*MATB)
#define SMEM_GEMM (2*STGB)

__device__ __forceinline__ void ld_mat(uint32_t dstbase, const bf16* __restrict__ src,
                                       int r0, int k0, int K, int tid)
{
    #pragma unroll
    for (int j = 0; j < 2; j++) {
        int idx = tid + j * 256;
        int row = idx >> 2, c = idx & 3;
        cp16(dstbase + row * 80 + c * 16, src + (size_t)(r0 + row) * K + k0 + c * 8);
    }
}

#define LOADSTAGE(t_, s_) do {                                         \
    uint32_t b_ = sb + (s_) * STGB;                                    \
    ld_mat(b_,            Ah, m0, (t_) * 32, K, tid);                  \
    ld_mat(b_ +     MATB, Al, m0, (t_) * 32, K, tid);                  \
    ld_mat(b_ + 2 * MATB, Bh, n0, (t_) * 32, K, tid);                  \
    ld_mat(b_ + 3 * MATB, Bl, n0, (t_) * 32, K, tid);                  \
    asm volatile("cp.async.commit_group;" ::: "memory");               \
} while (0)

__global__ void __launch_bounds__(256, 2) gemm_bf16_kernel(
    int sel, const float* __restrict__ bias, float* __restrict__ Cout,
    int K, int mode, int ldc)
{
    extern __shared__ __align__(128) char smraw[];
    bf16* sh = (bf16*)smraw;
    float* Csm = (float*)smraw;
    uint32_t sb = smem_u32(smraw);

    const bf16* Ah = (sel == 0) ? g_xhi : g_Yhi;
    const bf16* Al = (sel == 0) ? g_xlo : g_Ylo;
    const bf16* Bh = (sel == 0) ? g_Wah : g_Wph;
    const bf16* Bl = (sel == 0) ? g_Wal : g_Wpl;

    const int tid = threadIdx.x, wid = tid >> 5;
    const int warp_m = wid & 1, warp_n = wid >> 1;
    const int m0 = blockIdx.y * 128;
    const int n0 = blockIdx.x * 128;
    const int NT = K >> 5;

    wmma::fragment<wmma::accumulator, 16, 16, 16, float> facc[4][2];
    #pragma unroll
    for (int mi = 0; mi < 4; mi++)
        #pragma unroll
        for (int ni = 0; ni < 2; ni++)
            wmma::fill_fragment(facc[mi][ni], 0.0f);

    LOADSTAGE(0, 0);

    for (int t = 0; t < NT; t++) {
        if (t + 1 < NT) {
            LOADSTAGE(t + 1, (t + 1) & 1);
            asm volatile("cp.async.wait_group 1;" ::: "memory");
        } else {
            asm volatile("cp.async.wait_group 0;" ::: "memory");
        }
        __syncthreads();

        const bf16* Ahs = sh + (size_t)(t & 1) * (4 * MATH_);
        const bf16* Als = Ahs + MATH_;
        const bf16* Bhs = Ahs + 2 * MATH_;
        const bf16* Bls = Ahs + 3 * MATH_;

        #pragma unroll
        for (int kt = 0; kt < 32; kt += 16) {
            wmma::fragment<wmma::matrix_b, 16, 16, 16, bf16, wmma::col_major> fbh[2], fbl[2];
            #pragma unroll
            for (int ni = 0; ni < 2; ni++) {
                int nrow = warp_n * 32 + ni * 16;
                wmma::load_matrix_sync(fbh[ni], Bhs + nrow * LDH + kt, LDH);
                wmma::load_matrix_sync(fbl[ni], Bls + nrow * LDH + kt, LDH);
            }
            #pragma unroll
            for (int mi = 0; mi < 4; mi++) {
                wmma::fragment<wmma::matrix_a, 16, 16, 16, bf16, wmma::row_major> fah, fal;
                int mrow = warp_m * 64 + mi * 16;
                wmma::load_matrix_sync(fah, Ahs + mrow * LDH + kt, LDH);
                wmma::load_matrix_sync(fal, Als + mrow * LDH + kt, LDH);
                #pragma unroll
                for (int ni = 0; ni < 2; ni++) {
                    wmma::mma_sync(facc[mi][ni], fah, fbh[ni], facc[mi][ni]);
                    wmma::mma_sync(facc[mi][ni], fah, fbl[ni], facc[mi][ni]);
                    wmma::mma_sync(facc[mi][ni], fal, fbh[ni], facc[mi][ni]);
                }
            }
        }
        __syncthreads();
    }

    #pragma unroll
    for (int mi = 0; mi < 4; mi++)
        #pragma unroll
        for (int ni = 0; ni < 2; ni++)
            wmma::store_matrix_sync(
                Csm + (warp_m * 64 + mi * 16) * 132 + warp_n * 32 + ni * 16,
                facc[mi][ni], 132, wmma::mem_row_major);
    __syncthreads();

    for (int e = tid; e < 128 * 128; e += 256) {
        int mr = e >> 7, nc = e & 127;
        int m = m0 + mr, n = n0 + nc;
        float v = Csm[mr * 132 + nc] + bias[n];
        if (mode == 0) {
            int which = n >> 10;
            int cc = n & 1023;
            int h = cc >> 6, d = cc & 63;
            int bb = m >> 10, tt = m & 1023;
            size_t off = (size_t)(((bb * 16 + h) << 10) + tt) * 64 + d;
            if (which == 0) {
                g_Q[off] = v;
            } else if (which == 1) {
                bf16 hv = __float2bfloat16(v);
                g_Kbh[off] = hv;
                g_Kbl[off] = __float2bfloat16(v - __bfloat162float(hv));
            } else {
                g_V[off] = v;
            }
        } else {
            Cout[(size_t)m * ldc + n] = v;
        }
    }
}

// ---------------------------------------------------------------------------
// pos table via wmma 3-product, OUTPUT LAYOUT [bh][i][j], bf16 storage.
// K and E both read pre-split (pure uint4 smem copies, no conversion).
// ---------------------------------------------------------------------------
#define POS_SMEM (4*9216 + 64*68*4)

__global__ void __launch_bounds__(256) pos_kernel()
{
    extern __shared__ __align__(16) char smraw[];
    bf16* Kh = (bf16*)(smraw);
    bf16* Kl = (bf16*)(smraw + 9216);
    bf16* Eh = (bf16*)(smraw + 18432);
    bf16* El = (bf16*)(smraw + 27648);
    float* Ssm = (float*)(smraw + 36864);   // [64][68]

    const int j0 = blockIdx.x * 64;
    const int r0 = blockIdx.y * 64;
    if (j0 + r0 >= Tdim) return;
    const int bh = blockIdx.z, h = bh & 15;
    const int tid = threadIdx.x, wid = tid >> 5;
    const int wm = wid & 3, wn = wid >> 2;
    const int lane = tid & 31;

    {
        const size_t kb = ((size_t)bh * Tdim + j0) * 64;
        const size_t eb = ((size_t)h * Tdim + r0) * 64;
        #pragma unroll
        for (int q = 0; q < 2; q++) {
            int idx = tid + q * 256;
            int row = idx >> 3, ch = (idx & 7) * 8;
            *(uint4*)(Kh + row * 72 + ch) = *(const uint4*)(g_Kbh + kb + row * 64 + ch);
            *(uint4*)(Kl + row * 72 + ch) = *(const uint4*)(g_Kbl + kb + row * 64 + ch);
            *(uint4*)(Eh + row * 72 + ch) = *(const uint4*)(g_Eh + eb + row * 64 + ch);
            *(uint4*)(El + row * 72 + ch) = *(const uint4*)(g_El + eb + row * 64 + ch);
        }
    }
    __syncthreads();

    wmma::fragment<wmma::accumulator, 16, 16, 16, float> acc[2];
    #pragma unroll
    for (int ni = 0; ni < 2; ni++) wmma::fill_fragment(acc[ni], 0.0f);
    #pragma unroll
    for (int k = 0; k < 4; k++) {
        wmma::fragment<wmma::matrix_a, 16, 16, 16, bf16, wmma::row_major> fah, fal;
        wmma::load_matrix_sync(fah, Kh + (wm * 16) * 72 + k * 16, 72);
        wmma::load_matrix_sync(fal, Kl + (wm * 16) * 72 + k * 16, 72);
        #pragma unroll
        for (int ni = 0; ni < 2; ni++) {
            wmma::fragment<wmma::matrix_b, 16, 16, 16, bf16, wmma::col_major> fbh, fbl;
            wmma::load_matrix_sync(fbh, Eh + (wn * 32 + ni * 16) * 72 + k * 16, 72);
            wmma::load_matrix_sync(fbl, El + (wn * 32 + ni * 16) * 72 + k * 16, 72);
            wmma::mma_sync(acc[ni], fah, fbh, acc[ni]);
            wmma::mma_sync(acc[ni], fah, fbl, acc[ni]);
            wmma::mma_sync(acc[ni], fal, fbh, acc[ni]);
        }
    }
    #pragma unroll
    for (int ni = 0; ni < 2; ni++)
        wmma::store_matrix_sync(Ssm + (wm * 16) * 68 + wn * 32 + ni * 16, acc[ni], 68,
                                wmma::mem_row_major);
    __syncthreads();

    bf16* Pb = g_P + ((size_t)bh << 20);
    for (int il = wid; il < 127; il += 8) {
        int i = j0 + r0 + il;
        if (i >= Tdim) break;
        #pragma unroll
        for (int hf = 0; hf < 2; hf++) {
            int jc = lane + hf * 32;
            int r = il - jc;
            if (r >= 0 && r < 64)
                Pb[(size_t)i * Tdim + j0 + jc] = __float2bfloat16(Ssm[jc * 68 + r]);
        }
    }
}

// ---------------------------------------------------------------------------
// FA2-style flash attention (raw mma), pre-split bf16 operands, cp.async x2.
// ---------------------------------------------------------------------------
#define FLD 72
#define FST_B 36864
#define FL_SMEM (2*FST_B)

#define FLASH_LOAD(jt_, s_) do {                                               \
    size_t kbase_ = ((size_t)bh * 1024 + (size_t)(jt_) * 64) * 64;             \
    size_t vbase_ = (size_t)bh * 65536 + (size_t)(jt_) * 64;                   \
    _Pragma("unroll")                                                          \
    for (int q_ = 0; q_ < 8; q_++) {                                           \
        int idx_ = tid + q_ * 256;                                             \
        int mat_ = idx_ >> 9, rem_ = idx_ & 511;                               \
        int row_ = rem_ >> 3, c_ = rem_ & 7;                                   \
        const bf16* src_;                                                      \
        if (mat_ == 0)      src_ = g_Kbh + kbase_ + row_ * 64 + c_ * 8;        \
        else if (mat_ == 1) src_ = g_Kbl + kbase_ + row_ * 64 + c_ * 8;        \
        else if (mat_ == 2) src_ = g_Vth + vbase_ + (size_t)row_ * 1024 + c_ * 8; \
        else                src_ = g_Vtl + vbase_ + (size_t)row_ * 1024 + c_ * 8; \
        cp16(sb + (s_) * FST_B + mat_ * 9216 + row_ * 144 + c_ * 16, src_);    \
    }                                                                          \
    asm volatile("cp.async.commit_group;" ::: "memory");                       \
} while (0)

__global__ void __launch_bounds__(256) flash_kernel()
{
    extern __shared__ __align__(16) char fsm[];
    uint16_t* SMh = (uint16_t*)fsm;
    uint32_t sb = smem_u32(fsm);

    const int ib = (int)gridDim.x - 1 - (int)blockIdx.x;   // heavy CTAs first
    const int i0 = ib * 128;
    const int bh = blockIdx.y;
    const int b = bh >> 4, h = bh & 15;
    const int tid = threadIdx.x, wid = tid >> 5, lane = tid & 31;
    const int g = lane >> 2, tig = lane & 3;
    const int iW = i0 + wid * 16;
    const int rA = iW + g, rB = rA + 8;

    uint32_t qh[4][4], ql[4][4];
    {
        const float* Qg = g_Q + (size_t)bh * (Tdim * 64);
        #pragma unroll
        for (int kc = 0; kc < 4; kc++) {
            float2 v0 = *(const float2*)(Qg + (size_t)rA * 64 + kc * 16 + 2 * tig);
            float2 v1 = *(const float2*)(Qg + (size_t)rB * 64 + kc * 16 + 2 * tig);
            float2 v2 = *(const float2*)(Qg + (size_t)rA * 64 + kc * 16 + 2 * tig + 8);
            float2 v3 = *(const float2*)(Qg + (size_t)rB * 64 + kc * 16 + 2 * tig + 8);
            split2(v0.x * CSCALE, v0.y * CSCALE, qh[kc][0], ql[kc][0]);
            split2(v1.x * CSCALE, v1.y * CSCALE, qh[kc][1], ql[kc][1]);
            split2(v2.x * CSCALE, v2.y * CSCALE, qh[kc][2], ql[kc][2]);
            split2(v3.x * CSCALE, v3.y * CSCALE, qh[kc][3], ql[kc][3]);
        }
    }

    float o[8][4];
    #pragma unroll
    for (int t = 0; t < 8; t++) { o[t][0] = 0.f; o[t][1] = 0.f; o[t][2] = 0.f; o[t][3] = 0.f; }
    float mA = -1e30f, mB = -1e30f, lA = 0.f, lB = 0.f;

    const bf16* Pb = g_P + ((size_t)bh << 20);
    const int njt = (i0 + 128) >> 6;

    FLASH_LOAD(0, 0);

    for (int jt = 0; jt < njt; jt++) {
        const int j0 = jt << 6;
        if (jt + 1 < njt) {
            FLASH_LOAD(jt + 1, (jt + 1) & 1);
            asm volatile("cp.async.wait_group 1;" ::: "memory");
        } else {
            asm volatile("cp.async.wait_group 0;" ::: "memory");
        }
        __syncthreads();

        if (j0 <= iW + 15) {
            const uint16_t* Khs = SMh + (jt & 1) * (FST_B / 2);
            const uint16_t* Kls = Khs + 4608;
            const uint16_t* Vhs = Khs + 9216;
            const uint16_t* Vls = Khs + 13824;

            float s[8][4];
            #pragma unroll
            for (int t = 0; t < 8; t++) {
                int j = j0 + t * 8 + 2 * tig;
                __nv_bfloat162 b0 = *(const __nv_bfloat162*)(Pb + (size_t)rA * Tdim + j);
                __nv_bfloat162 b1 = *(const __nv_bfloat162*)(Pb + (size_t)rB * Tdim + j);
                s[t][0] = __bfloat162float(b0.x) * CSCALE;
                s[t][1] = __bfloat162float(b0.y) * CSCALE;
                s[t][2] = __bfloat162float(b1.x) * CSCALE;
                s[t][3] = __bfloat162float(b1.y) * CSCALE;
            }
            #pragma unroll
            for (int kc = 0; kc < 4; kc++) {
                #pragma unroll
                for (int t = 0; t < 8; t++) {
                    uint32_t kb0 = *(const uint32_t*)&Khs[(t * 8 + g) * FLD + kc * 16 + 2 * tig];
                    uint32_t kb1 = *(const uint32_t*)&Khs[(t * 8 + g) * FLD + kc * 16 + 2 * tig + 8];
                    uint32_t kl0 = *(const uint32_t*)&Kls[(t * 8 + g) * FLD + kc * 16 + 2 * tig];
                    uint32_t kl1 = *(const uint32_t*)&Kls[(t * 8 + g) * FLD + kc * 16 + 2 * tig + 8];
                    mma16816(s[t], qh[kc][0], qh[kc][1], qh[kc][2], qh[kc][3], kb0, kb1);
                    mma16816(s[t], qh[kc][0], qh[kc][1], qh[kc][2], qh[kc][3], kl0, kl1);
                    mma16816(s[t], ql[kc][0], ql[kc][1], ql[kc][2], ql[kc][3], kb0, kb1);
                }
            }

            if (j0 + 63 > iW) {
                #pragma unroll
                for (int t = 0; t < 8; t++) {
                    int j = j0 + t * 8 + 2 * tig;
                    if (j     > rA) s[t][0] = -3e38f;
                    if (j + 1 > rA) s[t][1] = -3e38f;
                    if (j     > rB) s[t][2] = -3e38f;
                    if (j + 1 > rB) s[t][3] = -3e38f;
                }
            }

            float mxA = -3e38f, mxB = -3e38f;
            #pragma unroll
            for (int t = 0; t < 8; t++) {
                mxA = fmaxf(mxA, fmaxf(s[t][0], s[t][1]));
                mxB = fmaxf(mxB, fmaxf(s[t][2], s[t][3]));
            }
            mxA = fmaxf(mxA, __shfl_xor_sync(0xffffffffu, mxA, 1));
            mxA = fmaxf(mxA, __shfl_xor_sync(0xffffffffu, mxA, 2));
            mxB = fmaxf(mxB, __shfl_xor_sync(0xffffffffu, mxB, 1));
            mxB = fmaxf(mxB, __shfl_xor_sync(0xffffffffu, mxB, 2));
            float nmA = fmaxf(mA, mxA), nmB = fmaxf(mB, mxB);
            float cA = ex2f(mA - nmA), cB = ex2f(mB - nmB);
            mA = nmA; mB = nmB;
            float sumA = 0.f, sumB = 0.f;
            #pragma unroll
            for (int t = 0; t < 8; t++) {
                s[t][0] = ex2f(s[t][0] - nmA); sumA += s[t][0];
                s[t][1] = ex2f(s[t][1] - nmA); sumA += s[t][1];
                s[t][2] = ex2f(s[t][2] - nmB); sumB += s[t][2];
                s[t][3] = ex2f(s[t][3] - nmB); sumB += s[t][3];
            }
            sumA += __shfl_xor_sync(0xffffffffu, sumA, 1);
            sumA += __shfl_xor_sync(0xffffffffu, sumA, 2);
            sumB += __shfl_xor_sync(0xffffffffu, sumB, 1);
            sumB += __shfl_xor_sync(0xffffffffu, sumB, 2);
            lA = lA * cA + sumA; lB = lB * cB + sumB;
            #pragma unroll
            for (int t = 0; t < 8; t++) {
                o[t][0] *= cA; o[t][1] *= cA; o[t][2] *= cB; o[t][3] *= cB;
            }

            #pragma unroll
            for (int kc = 0; kc < 4; kc++) {
                uint32_t ah[4], al[4];
                split2(s[2*kc][0],   s[2*kc][1],   ah[0], al[0]);
                split2(s[2*kc][2],   s[2*kc][3],   ah[1], al[1]);
                split2(s[2*kc+1][0], s[2*kc+1][1], ah[2], al[2]);
                split2(s[2*kc+1][2], s[2*kc+1][3], ah[3], al[3]);
                #pragma unroll
                for (int t = 0; t < 8; t++) {
                    uint32_t vb0 = *(const uint32_t*)&Vhs[(t * 8 + g) * FLD + kc * 16 + 2 * tig];
                    uint32_t vb1 = *(const uint32_t*)&Vhs[(t * 8 + g) * FLD + kc * 16 + 2 * tig + 8];
                    uint32_t vl0 = *(const uint32_t*)&Vls[(t * 8 + g) * FLD + kc * 16 + 2 * tig];
                    uint32_t vl1 = *(const uint32_t*)&Vls[(t * 8 + g) * FLD + kc * 16 + 2 * tig + 8];
                    mma16816(o[t], ah[0], ah[1], ah[2], ah[3], vb0, vb1);
                    mma16816(o[t], ah[0], ah[1], ah[2], ah[3], vl0, vl1);
                    mma16816(o[t], al[0], al[1], al[2], al[3], vb0, vb1);
                }
            }
        }
        __syncthreads();
    }

    float iA = 1.f / lA, iB = 1.f / lB;
    size_t baseA = ((size_t)(b * Tdim + rA)) * 1024 + h * 64;
    size_t baseB = ((size_t)(b * Tdim + rB)) * 1024 + h * 64;
    #pragma unroll
    for (int t = 0; t < 8; t++) {
        int d = t * 8 + 2 * tig;
        uint32_t hi, lo;
        split2(o[t][0] * iA, o[t][1] * iA, hi, lo);
        *(uint32_t*)&g_Yhi[baseA + d] = hi;
        *(uint32_t*)&g_Ylo[baseA + d] = lo;
        split2(o[t][2] * iB, o[t][3] * iB, hi, lo);
        *(uint32_t*)&g_Yhi[baseB + d] = hi;
        *(uint32_t*)&g_Ylo[baseB + d] = lo;
    }
}

// ---------------------------------------------------------------------------
extern "C" void kernel_launch(void* const* d_in, const int* in_sizes, int n_in,
                              void* d_out, int out_size)
{
    const float* x      = (const float*)d_in[0];
    const float* W_attn = (const float*)d_in[1];
    const float* b_attn = (const float*)d_in[2];
    const float* W_proj = (const float*)d_in[3];
    const float* b_proj = (const float*)d_in[4];
    const float* rel    = (const float*)d_in[5];
    float* out = (float*)d_out;

    cudaFuncSetAttribute(gemm_bf16_kernel,
                         cudaFuncAttributeMaxDynamicSharedMemorySize, SMEM_GEMM);
    cudaFuncSetAttribute(pos_kernel,
                         cudaFuncAttributeMaxDynamicSharedMemorySize, POS_SMEM);
    cudaFuncSetAttribute(flash_kernel,
                         cudaFuncAttributeMaxDynamicSharedMemorySize, FL_SMEM);

    // prep
    split_kernel<<<2048, 256>>>(x, 4096 * 1024);
    rel_split_kernel<<<512, 256>>>(rel);
    transpose_split_kernel<<<dim3(3072/32, 1024/32), 256>>>(W_attn, 0, 1024, 3072);
    transpose_split_kernel<<<dim3(1024/32, 1024/32), 256>>>(W_proj, 1, 1024, 1024);

    // 1) QKV (wmma x3) -> Q f32, K bf16 hi/lo (direct), V f32
    gemm_bf16_kernel<<<dim3(24, 32), 256, SMEM_GEMM>>>(0, b_attn, nullptr, 1024, 0, 0);

    // 1b) V -> bf16 hi/lo transposed
    v_prep_kernel<<<dim3(16, 64), 256>>>();

    // 2) relative-position table (wmma x3), [bh][i][j] layout, bf16
    pos_kernel<<<dim3(16, 16, 64), 256, POS_SMEM>>>();

    // 3) FA2 raw-mma flash with cp.async double buffering -> Yhi/Ylo
    flash_kernel<<<dim3(8, 64), 256, FL_SMEM>>>();

    // 4) out = Y @ W_proj + b_proj (wmma x3)
    gemm_bf16_kernel<<<dim3(8, 32), 256, SMEM_GEMM>>>(1, b_proj, out, 1024, 1, 1024);
}

// round 13
// speedup vs baseline: 1.0480x; 1.0216x over previous
#include <cuda_runtime.h>
#include <cuda_bf16.h>
#include <mma.h>
#include <cstdint>
#include <math.h>

using namespace nvcuda;
typedef __nv_bfloat16 bf16;

#define Tdim 1024
#define CSCALE 0.18033688011112f   /* 0.125 * log2(e) */

// Scratch (allocation-free __device__ globals; NEVER passed from host as args)
__device__ float g_Q[4194304];            // 16MB [bh][t][d] f32
__device__ float g_K[4194304];
__device__ float g_V[4194304];
__device__ bf16 g_P[67108864];            // 128MB [bh][i][j] bf16
__device__ bf16 g_xhi[4194304], g_xlo[4194304];
__device__ bf16 g_Wah[3145728], g_Wal[3145728];
__device__ bf16 g_Wph[1048576], g_Wpl[1048576];
__device__ bf16 g_Yhi[4194304], g_Ylo[4194304];
__device__ bf16 g_Eh[1048576], g_El[1048576];     // rel pre-split [h][r][d]
// pre-split attention operands
__device__ bf16 g_Kbh[4194304], g_Kbl[4194304];   // K hi/lo [bh][t][d]
__device__ bf16 g_Vth[4194304], g_Vtl[4194304];   // V hi/lo TRANSPOSED [bh][d][t]

// ---------------------------------------------------------------------------
__device__ __forceinline__ uint32_t smem_u32(const void* p) {
    uint32_t a;
    asm("{ .reg .u64 t; cvta.to.shared.u64 t, %1; cvt.u32.u64 %0, t; }" : "=r"(a) : "l"(p));
    return a;
}
__device__ __forceinline__ void cp16(uint32_t dst, const void* src) {
    asm volatile("cp.async.cg.shared.global [%0], [%1], 16;" :: "r"(dst), "l"(src) : "memory");
}
__device__ __forceinline__ float ex2f(float x) {
    float r; asm("ex2.approx.ftz.f32 %0, %1;" : "=f"(r) : "f"(x)); return r;
}
__device__ __forceinline__ void mma16816(float* c, uint32_t a0, uint32_t a1, uint32_t a2,
                                         uint32_t a3, uint32_t b0, uint32_t b1) {
    asm volatile("mma.sync.aligned.m16n8k16.row.col.f32.bf16.bf16.f32 "
        "{%0,%1,%2,%3}, {%4,%5,%6,%7}, {%8,%9}, {%0,%1,%2,%3};"
        : "+f"(c[0]), "+f"(c[1]), "+f"(c[2]), "+f"(c[3])
        : "r"(a0), "r"(a1), "r"(a2), "r"(a3), "r"(b0), "r"(b1));
}
__device__ __forceinline__ void split2(float x, float y, uint32_t& hi, uint32_t& lo) {
    bf16 hx = __float2bfloat16(x), hy = __float2bfloat16(y);
    hi = (uint32_t)__bfloat16_as_ushort(hx) | ((uint32_t)__bfloat16_as_ushort(hy) << 16);
    bf16 lx = __float2bfloat16(x - __bfloat162float(hx));
    bf16 ly = __float2bfloat16(y - __bfloat162float(hy));
    lo = (uint32_t)__bfloat16_as_ushort(lx) | ((uint32_t)__bfloat16_as_ushort(ly) << 16);
}

// ---------------------------------------------------------------------------
// prep: bf16 hi/lo split of x; rel pre-split; transpose+split weights
// ---------------------------------------------------------------------------
__global__ void __launch_bounds__(256) split_kernel(const float* __restrict__ s, int n)
{
    for (int i = blockIdx.x * blockDim.x + threadIdx.x; i < n; i += gridDim.x * blockDim.x) {
        float x = s[i];
        bf16 h = __float2bfloat16(x);
        g_xhi[i] = h;
        g_xlo[i] = __float2bfloat16(x - __bfloat162float(h));
    }
}

__global__ void __launch_bounds__(256) rel_split_kernel(const float* __restrict__ rel)
{
    for (int i = blockIdx.x * blockDim.x + threadIdx.x; i < 1048576; i += gridDim.x * blockDim.x) {
        float x = rel[i];
        bf16 h = __float2bfloat16(x);
        g_Eh[i] = h;
        g_El[i] = __float2bfloat16(x - __bfloat162float(h));
    }
}

__global__ void __launch_bounds__(256) transpose_split_kernel(
    const float* __restrict__ W, int which, int K, int N)
{
    bf16* Th = (which == 0) ? g_Wah : g_Wph;
    bf16* Tl = (which == 0) ? g_Wal : g_Wpl;
    __shared__ float t[32][33];
    int n0 = blockIdx.x * 32, k0 = blockIdx.y * 32;
    int tx = threadIdx.x & 31, ty = threadIdx.x >> 5;
    #pragma unroll
    for (int i = 0; i < 32; i += 8)
        t[ty + i][tx] = W[(size_t)(k0 + ty + i) * N + n0 + tx];
    __syncthreads();
    #pragma unroll
    for (int i = 0; i < 32; i += 8) {
        float v = t[tx][ty + i];
        bf16 h = __float2bfloat16(v);
        size_t o = (size_t)(n0 + ty + i) * K + k0 + tx;
        Th[o] = h;
        Tl[o] = __float2bfloat16(v - __bfloat162float(h));
    }
}

// K: elementwise f32 -> bf16 hi/lo, same [bh][t][d] layout  (R10 config)
__global__ void __launch_bounds__(256) k_split_kernel()
{
    for (int i = blockIdx.x * 256 + threadIdx.x; i < 4194304; i += gridDim.x * 256) {
        float x = g_K[i];
        bf16 hv = __float2bfloat16(x);
        g_Kbh[i] = hv;
        g_Kbl[i] = __float2bfloat16(x - __bfloat162float(hv));
    }
}

// V: f32 [bh][t][d] -> bf16 hi/lo TRANSPOSED [bh][d][t]  (R10 config)
__global__ void __launch_bounds__(256) v_transpose_kernel()
{
    __shared__ float ts[64][65];
    const int t0 = blockIdx.x * 64;
    const int bh = blockIdx.y;
    const float* Vg = g_V + ((size_t)bh * 1024 + t0) * 64;
    const int tid = threadIdx.x;
    #pragma unroll
    for (int q = 0; q < 4; q++) {
        int idx = tid + q * 256;
        int row = idx >> 4, c4 = (idx & 15) * 4;
        float4 v = *(const float4*)(Vg + (size_t)row * 64 + c4);
        ts[row][c4+0] = v.x; ts[row][c4+1] = v.y; ts[row][c4+2] = v.z; ts[row][c4+3] = v.w;
    }
    __syncthreads();
    #pragma unroll
    for (int q = 0; q < 4; q++) {
        int idx = tid + q * 256;
        int d = idx >> 4, t4 = (idx & 15) * 4;
        float v0 = ts[t4+0][d], v1 = ts[t4+1][d], v2 = ts[t4+2][d], v3 = ts[t4+3][d];
        uint32_t h0, l0, h1, l1;
        split2(v0, v1, h0, l0);
        split2(v2, v3, h1, l1);
        size_t dst = (size_t)bh * 65536 + (size_t)d * 1024 + t0 + t4;
        *(uint32_t*)&g_Vth[dst]     = h0;
        *(uint32_t*)&g_Vth[dst + 2] = h1;
        *(uint32_t*)&g_Vtl[dst]     = l0;
        *(uint32_t*)&g_Vtl[dst + 2] = l1;
    }
}

// ---------------------------------------------------------------------------
// bf16 3-product WMMA GEMM — EXACT round-10 kernel (measured 274/90us).
// ---------------------------------------------------------------------------
#define LDH 40
#define MATH_ (128*LDH)
#define MATB (MATH_*2)
#define STGB (4*MATB)
#define SMEM_GEMM (2*STGB)

__device__ __forceinline__ void ld_mat(uint32_t dstbase, const bf16* __restrict__ src,
                                       int r0, int k0, int K, int tid)
{
    #pragma unroll
    for (int j = 0; j < 2; j++) {
        int idx = tid + j * 256;
        int row = idx >> 2, c = idx & 3;
        cp16(dstbase + row * 80 + c * 16, src + (size_t)(r0 + row) * K + k0 + c * 8);
    }
}

#define LOADSTAGE(t_, s_) do {                                         \
    uint32_t b_ = sb + (s_) * STGB;                                    \
    ld_mat(b_,            Ah, m0, (t_) * 32, K, tid);                  \
    ld_mat(b_ +     MATB, Al, m0, (t_) * 32, K, tid);                  \
    ld_mat(b_ + 2 * MATB, Bh, n0, (t_) * 32, K, tid);                  \
    ld_mat(b_ + 3 * MATB, Bl, n0, (t_) * 32, K, tid);                  \
    asm volatile("cp.async.commit_group;" ::: "memory");               \
} while (0)

__global__ void __launch_bounds__(256, 2) gemm_bf16_kernel(
    int sel, const float* __restrict__ bias, float* __restrict__ Cout,
    int K, int mode, int ldc)
{
    extern __shared__ __align__(128) char smraw[];
    bf16* sh = (bf16*)smraw;
    float* Csm = (float*)smraw;
    uint32_t sb = smem_u32(smraw);

    const bf16* Ah = (sel == 0) ? g_xhi : g_Yhi;
    const bf16* Al = (sel == 0) ? g_xlo : g_Ylo;
    const bf16* Bh = (sel == 0) ? g_Wah : g_Wph;
    const bf16* Bl = (sel == 0) ? g_Wal : g_Wpl;

    const int tid = threadIdx.x, wid = tid >> 5;
    const int warp_m = wid & 1, warp_n = wid >> 1;
    const int m0 = blockIdx.y * 128;
    const int n0 = blockIdx.x * 128;
    const int NT = K >> 5;

    wmma::fragment<wmma::accumulator, 16, 16, 16, float> facc[4][2];
    #pragma unroll
    for (int mi = 0; mi < 4; mi++)
        #pragma unroll
        for (int ni = 0; ni < 2; ni++)
            wmma::fill_fragment(facc[mi][ni], 0.0f);

    LOADSTAGE(0, 0);

    for (int t = 0; t < NT; t++) {
        if (t + 1 < NT) {
            LOADSTAGE(t + 1, (t + 1) & 1);
            asm volatile("cp.async.wait_group 1;" ::: "memory");
        } else {
            asm volatile("cp.async.wait_group 0;" ::: "memory");
        }
        __syncthreads();

        const bf16* Ahs = sh + (size_t)(t & 1) * (4 * MATH_);
        const bf16* Als = Ahs + MATH_;
        const bf16* Bhs = Ahs + 2 * MATH_;
        const bf16* Bls = Ahs + 3 * MATH_;

        #pragma unroll
        for (int kt = 0; kt < 32; kt += 16) {
            wmma::fragment<wmma::matrix_b, 16, 16, 16, bf16, wmma::col_major> fbh[2], fbl[2];
            #pragma unroll
            for (int ni = 0; ni < 2; ni++) {
                int nrow = warp_n * 32 + ni * 16;
                wmma::load_matrix_sync(fbh[ni], Bhs + nrow * LDH + kt, LDH);
                wmma::load_matrix_sync(fbl[ni], Bls + nrow * LDH + kt, LDH);
            }
            #pragma unroll
            for (int mi = 0; mi < 4; mi++) {
                wmma::fragment<wmma::matrix_a, 16, 16, 16, bf16, wmma::row_major> fah, fal;
                int mrow = warp_m * 64 + mi * 16;
                wmma::load_matrix_sync(fah, Ahs + mrow * LDH + kt, LDH);
                wmma::load_matrix_sync(fal, Als + mrow * LDH + kt, LDH);
                #pragma unroll
                for (int ni = 0; ni < 2; ni++) {
                    wmma::mma_sync(facc[mi][ni], fah, fbh[ni], facc[mi][ni]);
                    wmma::mma_sync(facc[mi][ni], fah, fbl[ni], facc[mi][ni]);
                    wmma::mma_sync(facc[mi][ni], fal, fbh[ni], facc[mi][ni]);
                }
            }
        }
        __syncthreads();
    }

    #pragma unroll
    for (int mi = 0; mi < 4; mi++)
        #pragma unroll
        for (int ni = 0; ni < 2; ni++)
            wmma::store_matrix_sync(
                Csm + (warp_m * 64 + mi * 16) * 132 + warp_n * 32 + ni * 16,
                facc[mi][ni], 132, wmma::mem_row_major);
    __syncthreads();

    for (int e = tid; e < 128 * 128; e += 256) {
        int mr = e >> 7, nc = e & 127;
        int m = m0 + mr, n = n0 + nc;
        float v = Csm[mr * 132 + nc] + bias[n];
        if (mode == 0) {
            int which = n >> 10;
            int cc = n & 1023;
            int h = cc >> 6, d = cc & 63;
            float* dst = (which == 0) ? g_Q : ((which == 1) ? g_K : g_V);
            int bb = m >> 10, tt = m & 1023;
            dst[(size_t)(((bb * 16 + h) << 10) + tt) * 64 + d] = v;
        } else {
            Cout[(size_t)m * ldc + n] = v;
        }
    }
}

// ---------------------------------------------------------------------------
// pos table via wmma 3-product, OUTPUT LAYOUT [bh][i][j], bf16 storage.
// K and E both read pre-split (pure uint4 smem copies, no conversion).
// ---------------------------------------------------------------------------
#define POS_SMEM (4*9216 + 64*68*4)

__global__ void __launch_bounds__(256) pos_kernel()
{
    extern __shared__ __align__(16) char smraw[];
    bf16* Kh = (bf16*)(smraw);
    bf16* Kl = (bf16*)(smraw + 9216);
    bf16* Eh = (bf16*)(smraw + 18432);
    bf16* El = (bf16*)(smraw + 27648);
    float* Ssm = (float*)(smraw + 36864);   // [64][68]

    const int j0 = blockIdx.x * 64;
    const int r0 = blockIdx.y * 64;
    if (j0 + r0 >= Tdim) return;
    const int bh = blockIdx.z, h = bh & 15;
    const int tid = threadIdx.x, wid = tid >> 5;
    const int wm = wid & 3, wn = wid >> 2;
    const int lane = tid & 31;

    {
        const size_t kb = ((size_t)bh * Tdim + j0) * 64;
        const size_t eb = ((size_t)h * Tdim + r0) * 64;
        #pragma unroll
        for (int q = 0; q < 2; q++) {
            int idx = tid + q * 256;
            int row = idx >> 3, ch = (idx & 7) * 8;
            *(uint4*)(Kh + row * 72 + ch) = *(const uint4*)(g_Kbh + kb + row * 64 + ch);
            *(uint4*)(Kl + row * 72 + ch) = *(const uint4*)(g_Kbl + kb + row * 64 + ch);
            *(uint4*)(Eh + row * 72 + ch) = *(const uint4*)(g_Eh + eb + row * 64 + ch);
            *(uint4*)(El + row * 72 + ch) = *(const uint4*)(g_El + eb + row * 64 + ch);
        }
    }
    __syncthreads();

    wmma::fragment<wmma::accumulator, 16, 16, 16, float> acc[2];
    #pragma unroll
    for (int ni = 0; ni < 2; ni++) wmma::fill_fragment(acc[ni], 0.0f);
    #pragma unroll
    for (int k = 0; k < 4; k++) {
        wmma::fragment<wmma::matrix_a, 16, 16, 16, bf16, wmma::row_major> fah, fal;
        wmma::load_matrix_sync(fah, Kh + (wm * 16) * 72 + k * 16, 72);
        wmma::load_matrix_sync(fal, Kl + (wm * 16) * 72 + k * 16, 72);
        #pragma unroll
        for (int ni = 0; ni < 2; ni++) {
            wmma::fragment<wmma::matrix_b, 16, 16, 16, bf16, wmma::col_major> fbh, fbl;
            wmma::load_matrix_sync(fbh, Eh + (wn * 32 + ni * 16) * 72 + k * 16, 72);
            wmma::load_matrix_sync(fbl, El + (wn * 32 + ni * 16) * 72 + k * 16, 72);
            wmma::mma_sync(acc[ni], fah, fbh, acc[ni]);
            wmma::mma_sync(acc[ni], fah, fbl, acc[ni]);
            wmma::mma_sync(acc[ni], fal, fbh, acc[ni]);
        }
    }
    #pragma unroll
    for (int ni = 0; ni < 2; ni++)
        wmma::store_matrix_sync(Ssm + (wm * 16) * 68 + wn * 32 + ni * 16, acc[ni], 68,
                                wmma::mem_row_major);
    __syncthreads();

    bf16* Pb = g_P + ((size_t)bh << 20);
    for (int il = wid; il < 127; il += 8) {
        int i = j0 + r0 + il;
        if (i >= Tdim) break;
        #pragma unroll
        for (int hf = 0; hf < 2; hf++) {
            int jc = lane + hf * 32;
            int r = il - jc;
            if (r >= 0 && r < 64)
                Pb[(size_t)i * Tdim + j0 + jc] = __float2bfloat16(Ssm[jc * 68 + r]);
        }
    }
}

// ---------------------------------------------------------------------------
// FA2-style flash attention (raw mma), pre-split bf16 operands, cp.async x2.
// Mainloop identical to R10 except the bias read is bf16.
// ---------------------------------------------------------------------------
#define FLD 72
#define FST_B 36864
#define FL_SMEM (2*FST_B)

#define FLASH_LOAD(jt_, s_) do {                                               \
    size_t kbase_ = ((size_t)bh * 1024 + (size_t)(jt_) * 64) * 64;             \
    size_t vbase_ = (size_t)bh * 65536 + (size_t)(jt_) * 64;                   \
    _Pragma("unroll")                                                          \
    for (int q_ = 0; q_ < 8; q_++) {                                           \
        int idx_ = tid + q_ * 256;                                             \
        int mat_ = idx_ >> 9, rem_ = idx_ & 511;                               \
        int row_ = rem_ >> 3, c_ = rem_ & 7;                                   \
        const bf16* src_;                                                      \
        if (mat_ == 0)      src_ = g_Kbh + kbase_ + row_ * 64 + c_ * 8;        \
        else if (mat_ == 1) src_ = g_Kbl + kbase_ + row_ * 64 + c_ * 8;        \
        else if (mat_ == 2) src_ = g_Vth + vbase_ + (size_t)row_ * 1024 + c_ * 8; \
        else                src_ = g_Vtl + vbase_ + (size_t)row_ * 1024 + c_ * 8; \
        cp16(sb + (s_) * FST_B + mat_ * 9216 + row_ * 144 + c_ * 16, src_);    \
    }                                                                          \
    asm volatile("cp.async.commit_group;" ::: "memory");                       \
} while (0)

__global__ void __launch_bounds__(256) flash_kernel()
{
    extern __shared__ __align__(16) char fsm[];
    uint16_t* SMh = (uint16_t*)fsm;
    uint32_t sb = smem_u32(fsm);

    const int ib = (int)gridDim.x - 1 - (int)blockIdx.x;   // heavy CTAs first
    const int i0 = ib * 128;
    const int bh = blockIdx.y;
    const int b = bh >> 4, h = bh & 15;
    const int tid = threadIdx.x, wid = tid >> 5, lane = tid & 31;
    const int g = lane >> 2, tig = lane & 3;
    const int iW = i0 + wid * 16;
    const int rA = iW + g, rB = rA + 8;

    uint32_t qh[4][4], ql[4][4];
    {
        const float* Qg = g_Q + (size_t)bh * (Tdim * 64);
        #pragma unroll
        for (int kc = 0; kc < 4; kc++) {
            float2 v0 = *(const float2*)(Qg + (size_t)rA * 64 + kc * 16 + 2 * tig);
            float2 v1 = *(const float2*)(Qg + (size_t)rB * 64 + kc * 16 + 2 * tig);
            float2 v2 = *(const float2*)(Qg + (size_t)rA * 64 + kc * 16 + 2 * tig + 8);
            float2 v3 = *(const float2*)(Qg + (size_t)rB * 64 + kc * 16 + 2 * tig + 8);
            split2(v0.x * CSCALE, v0.y * CSCALE, qh[kc][0], ql[kc][0]);
            split2(v1.x * CSCALE, v1.y * CSCALE, qh[kc][1], ql[kc][1]);
            split2(v2.x * CSCALE, v2.y * CSCALE, qh[kc][2], ql[kc][2]);
            split2(v3.x * CSCALE, v3.y * CSCALE, qh[kc][3], ql[kc][3]);
        }
    }

    float o[8][4];
    #pragma unroll
    for (int t = 0; t < 8; t++) { o[t][0] = 0.f; o[t][1] = 0.f; o[t][2] = 0.f; o[t][3] = 0.f; }
    float mA = -1e30f, mB = -1e30f, lA = 0.f, lB = 0.f;

    const bf16* Pb = g_P + ((size_t)bh << 20);
    const int njt = (i0 + 128) >> 6;

    FLASH_LOAD(0, 0);

    for (int jt = 0; jt < njt; jt++) {
        const int j0 = jt << 6;
        if (jt + 1 < njt) {
            FLASH_LOAD(jt + 1, (jt + 1) & 1);
            asm volatile("cp.async.wait_group 1;" ::: "memory");
        } else {
            asm volatile("cp.async.wait_group 0;" ::: "memory");
        }
        __syncthreads();

        if (j0 <= iW + 15) {
            const uint16_t* Khs = SMh + (jt & 1) * (FST_B / 2);
            const uint16_t* Kls = Khs + 4608;
            const uint16_t* Vhs = Khs + 9216;
            const uint16_t* Vls = Khs + 13824;

            float s[8][4];
            #pragma unroll
            for (int t = 0; t < 8; t++) {
                int j = j0 + t * 8 + 2 * tig;
                __nv_bfloat162 b0 = *(const __nv_bfloat162*)(Pb + (size_t)rA * Tdim + j);
                __nv_bfloat162 b1 = *(const __nv_bfloat162*)(Pb + (size_t)rB * Tdim + j);
                s[t][0] = __bfloat162float(b0.x) * CSCALE;
                s[t][1] = __bfloat162float(b0.y) * CSCALE;
                s[t][2] = __bfloat162float(b1.x) * CSCALE;
                s[t][3] = __bfloat162float(b1.y) * CSCALE;
            }
            #pragma unroll
            for (int kc = 0; kc < 4; kc++) {
                #pragma unroll
                for (int t = 0; t < 8; t++) {
                    uint32_t kb0 = *(const uint32_t*)&Khs[(t * 8 + g) * FLD + kc * 16 + 2 * tig];
                    uint32_t kb1 = *(const uint32_t*)&Khs[(t * 8 + g) * FLD + kc * 16 + 2 * tig + 8];
                    uint32_t kl0 = *(const uint32_t*)&Kls[(t * 8 + g) * FLD + kc * 16 + 2 * tig];
                    uint32_t kl1 = *(const uint32_t*)&Kls[(t * 8 + g) * FLD + kc * 16 + 2 * tig + 8];
                    mma16816(s[t], qh[kc][0], qh[kc][1], qh[kc][2], qh[kc][3], kb0, kb1);
                    mma16816(s[t], qh[kc][0], qh[kc][1], qh[kc][2], qh[kc][3], kl0, kl1);
                    mma16816(s[t], ql[kc][0], ql[kc][1], ql[kc][2], ql[kc][3], kb0, kb1);
                }
            }

            if (j0 + 63 > iW) {
                #pragma unroll
                for (int t = 0; t < 8; t++) {
                    int j = j0 + t * 8 + 2 * tig;
                    if (j     > rA) s[t][0] = -3e38f;
                    if (j + 1 > rA) s[t][1] = -3e38f;
                    if (j     > rB) s[t][2] = -3e38f;
                    if (j + 1 > rB) s[t][3] = -3e38f;
                }
            }

            float mxA = -3e38f, mxB = -3e38f;
            #pragma unroll
            for (int t = 0; t < 8; t++) {
                mxA = fmaxf(mxA, fmaxf(s[t][0], s[t][1]));
                mxB = fmaxf(mxB, fmaxf(s[t][2], s[t][3]));
            }
            mxA = fmaxf(mxA, __shfl_xor_sync(0xffffffffu, mxA, 1));
            mxA = fmaxf(mxA, __shfl_xor_sync(0xffffffffu, mxA, 2));
            mxB = fmaxf(mxB, __shfl_xor_sync(0xffffffffu, mxB, 1));
            mxB = fmaxf(mxB, __shfl_xor_sync(0xffffffffu, mxB, 2));
            float nmA = fmaxf(mA, mxA), nmB = fmaxf(mB, mxB);
            float cA = ex2f(mA - nmA), cB = ex2f(mB - nmB);
            mA = nmA; mB = nmB;
            float sumA = 0.f, sumB = 0.f;
            #pragma unroll
            for (int t = 0; t < 8; t++) {
                s[t][0] = ex2f(s[t][0] - nmA); sumA += s[t][0];
                s[t][1] = ex2f(s[t][1] - nmA); sumA += s[t][1];
                s[t][2] = ex2f(s[t][2] - nmB); sumB += s[t][2];
                s[t][3] = ex2f(s[t][3] - nmB); sumB += s[t][3];
            }
            sumA += __shfl_xor_sync(0xffffffffu, sumA, 1);
            sumA += __shfl_xor_sync(0xffffffffu, sumA, 2);
            sumB += __shfl_xor_sync(0xffffffffu, sumB, 1);
            sumB += __shfl_xor_sync(0xffffffffu, sumB, 2);
            lA = lA * cA + sumA; lB = lB * cB + sumB;
            #pragma unroll
            for (int t = 0; t < 8; t++) {
                o[t][0] *= cA; o[t][1] *= cA; o[t][2] *= cB; o[t][3] *= cB;
            }

            #pragma unroll
            for (int kc = 0; kc < 4; kc++) {
                uint32_t ah[4], al[4];
                split2(s[2*kc][0],   s[2*kc][1],   ah[0], al[0]);
                split2(s[2*kc][2],   s[2*kc][3],   ah[1], al[1]);
                split2(s[2*kc+1][0], s[2*kc+1][1], ah[2], al[2]);
                split2(s[2*kc+1][2], s[2*kc+1][3], ah[3], al[3]);
                #pragma unroll
                for (int t = 0; t < 8; t++) {
                    uint32_t vb0 = *(const uint32_t*)&Vhs[(t * 8 + g) * FLD + kc * 16 + 2 * tig];
                    uint32_t vb1 = *(const uint32_t*)&Vhs[(t * 8 + g) * FLD + kc * 16 + 2 * tig + 8];
                    uint32_t vl0 = *(const uint32_t*)&Vls[(t * 8 + g) * FLD + kc * 16 + 2 * tig];
                    uint32_t vl1 = *(const uint32_t*)&Vls[(t * 8 + g) * FLD + kc * 16 + 2 * tig + 8];
                    mma16816(o[t], ah[0], ah[1], ah[2], ah[3], vb0, vb1);
                    mma16816(o[t], ah[0], ah[1], ah[2], ah[3], vl0, vl1);
                    mma16816(o[t], al[0], al[1], al[2], al[3], vb0, vb1);
                }
            }
        }
        __syncthreads();
    }

    float iA = 1.f / lA, iB = 1.f / lB;
    size_t baseA = ((size_t)(b * Tdim + rA)) * 1024 + h * 64;
    size_t baseB = ((size_t)(b * Tdim + rB)) * 1024 + h * 64;
    #pragma unroll
    for (int t = 0; t < 8; t++) {
        int d = t * 8 + 2 * tig;
        uint32_t hi, lo;
        split2(o[t][0] * iA, o[t][1] * iA, hi, lo);
        *(uint32_t*)&g_Yhi[baseA + d] = hi;
        *(uint32_t*)&g_Ylo[baseA + d] = lo;
        split2(o[t][2] * iB, o[t][3] * iB, hi, lo);
        *(uint32_t*)&g_Yhi[baseB + d] = hi;
        *(uint32_t*)&g_Ylo[baseB + d] = lo;
    }
}

// ---------------------------------------------------------------------------
extern "C" void kernel_launch(void* const* d_in, const int* in_sizes, int n_in,
                              void* d_out, int out_size)
{
    const float* x      = (const float*)d_in[0];
    const float* W_attn = (const float*)d_in[1];
    const float* b_attn = (const float*)d_in[2];
    const float* W_proj = (const float*)d_in[3];
    const float* b_proj = (const float*)d_in[4];
    const float* rel    = (const float*)d_in[5];
    float* out = (float*)d_out;

    cudaFuncSetAttribute(gemm_bf16_kernel,
                         cudaFuncAttributeMaxDynamicSharedMemorySize, SMEM_GEMM);
    cudaFuncSetAttribute(pos_kernel,
                         cudaFuncAttributeMaxDynamicSharedMemorySize, POS_SMEM);
    cudaFuncSetAttribute(flash_kernel,
                         cudaFuncAttributeMaxDynamicSharedMemorySize, FL_SMEM);

    // prep
    split_kernel<<<2048, 256>>>(x, 4096 * 1024);
    rel_split_kernel<<<512, 256>>>(rel);
    transpose_split_kernel<<<dim3(3072/32, 1024/32), 256>>>(W_attn, 0, 1024, 3072);
    transpose_split_kernel<<<dim3(1024/32, 1024/32), 256>>>(W_proj, 1, 1024, 1024);

    // 1) QKV (wmma x3) -> f32 Q/K/V scatter (R10 epilogue)
    gemm_bf16_kernel<<<dim3(24, 32), 256, SMEM_GEMM>>>(0, b_attn, nullptr, 1024, 0, 0);

    // 1b) pre-split K (hi/lo) and V (hi/lo transposed) for flash (R10 config)
    k_split_kernel<<<2048, 256>>>();
    v_transpose_kernel<<<dim3(16, 64), 256>>>();

    // 2) relative-position table (wmma x3), [bh][i][j] layout, bf16, pre-split E
    pos_kernel<<<dim3(16, 16, 64), 256, POS_SMEM>>>();

    // 3) FA2 raw-mma flash with cp.async double buffering -> Yhi/Ylo
    flash_kernel<<<dim3(8, 64), 256, FL_SMEM>>>();

    // 4) out = Y @ W_proj + b_proj (wmma x3)
    gemm_bf16_kernel<<<dim3(8, 32), 256, SMEM_GEMM>>>(1, b_proj, out, 1024, 1, 1024);
}

// round 15
// speedup vs baseline: 1.0583x; 1.0098x over previous
#include <cuda_runtime.h>
#include <cuda_bf16.h>
#include <mma.h>
#include <cstdint>
#include <math.h>

using namespace nvcuda;
typedef __nv_bfloat16 bf16;

#define Tdim 1024
#define CSCALE 0.18033688011112f   /* 0.125 * log2(e) */

// Scratch (allocation-free __device__ globals; NEVER passed from host as args)
__device__ float g_Q[4194304];            // 16MB [bh][t][d] f32
__device__ float g_K[4194304];
__device__ float g_V[4194304];
__device__ bf16 g_P[67108864];            // 128MB [bh][i][j] bf16
__device__ bf16 g_xhi[4194304], g_xlo[4194304];
__device__ bf16 g_Wah[3145728], g_Wal[3145728];
__device__ bf16 g_Wph[1048576], g_Wpl[1048576];
__device__ bf16 g_Yhi[4194304], g_Ylo[4194304];
__device__ bf16 g_Eh[1048576], g_El[1048576];     // rel pre-split [h][r][d]
// pre-split attention operands
__device__ bf16 g_Kbh[4194304], g_Kbl[4194304];   // K hi/lo [bh][t][d]
__device__ bf16 g_Vth[4194304], g_Vtl[4194304];   // V hi/lo TRANSPOSED [bh][d][t]

// ---------------------------------------------------------------------------
__device__ __forceinline__ uint32_t smem_u32(const void* p) {
    uint32_t a;
    asm("{ .reg .u64 t; cvta.to.shared.u64 t, %1; cvt.u32.u64 %0, t; }" : "=r"(a) : "l"(p));
    return a;
}
__device__ __forceinline__ void cp16(uint32_t dst, const void* src) {
    asm volatile("cp.async.cg.shared.global [%0], [%1], 16;" :: "r"(dst), "l"(src) : "memory");
}
__device__ __forceinline__ float ex2f(float x) {
    float r; asm("ex2.approx.ftz.f32 %0, %1;" : "=f"(r) : "f"(x)); return r;
}
__device__ __forceinline__ void mma16816(float* c, uint32_t a0, uint32_t a1, uint32_t a2,
                                         uint32_t a3, uint32_t b0, uint32_t b1) {
    asm volatile("mma.sync.aligned.m16n8k16.row.col.f32.bf16.bf16.f32 "
        "{%0,%1,%2,%3}, {%4,%5,%6,%7}, {%8,%9}, {%0,%1,%2,%3};"
        : "+f"(c[0]), "+f"(c[1]), "+f"(c[2]), "+f"(c[3])
        : "r"(a0), "r"(a1), "r"(a2), "r"(a3), "r"(b0), "r"(b1));
}
__device__ __forceinline__ void split2(float x, float y, uint32_t& hi, uint32_t& lo) {
    bf16 hx = __float2bfloat16(x), hy = __float2bfloat16(y);
    hi = (uint32_t)__bfloat16_as_ushort(hx) | ((uint32_t)__bfloat16_as_ushort(hy) << 16);
    bf16 lx = __float2bfloat16(x - __bfloat162float(hx));
    bf16 ly = __float2bfloat16(y - __bfloat162float(hy));
    lo = (uint32_t)__bfloat16_as_ushort(lx) | ((uint32_t)__bfloat16_as_ushort(ly) << 16);
}

// ---------------------------------------------------------------------------
// prep kernels (R13 config)
// ---------------------------------------------------------------------------
__global__ void __launch_bounds__(256) split_kernel(const float* __restrict__ s, int n)
{
    for (int i = blockIdx.x * blockDim.x + threadIdx.x; i < n; i += gridDim.x * blockDim.x) {
        float x = s[i];
        bf16 h = __float2bfloat16(x);
        g_xhi[i] = h;
        g_xlo[i] = __float2bfloat16(x - __bfloat162float(h));
    }
}

__global__ void __launch_bounds__(256) rel_split_kernel(const float* __restrict__ rel)
{
    for (int i = blockIdx.x * blockDim.x + threadIdx.x; i < 1048576; i += gridDim.x * blockDim.x) {
        float x = rel[i];
        bf16 h = __float2bfloat16(x);
        g_Eh[i] = h;
        g_El[i] = __float2bfloat16(x - __bfloat162float(h));
    }
}

__global__ void __launch_bounds__(256) transpose_split_kernel(
    const float* __restrict__ W, int which, int K, int N)
{
    bf16* Th = (which == 0) ? g_Wah : g_Wph;
    bf16* Tl = (which == 0) ? g_Wal : g_Wpl;
    __shared__ float t[32][33];
    int n0 = blockIdx.x * 32, k0 = blockIdx.y * 32;
    int tx = threadIdx.x & 31, ty = threadIdx.x >> 5;
    #pragma unroll
    for (int i = 0; i < 32; i += 8)
        t[ty + i][tx] = W[(size_t)(k0 + ty + i) * N + n0 + tx];
    __syncthreads();
    #pragma unroll
    for (int i = 0; i < 32; i += 8) {
        float v = t[tx][ty + i];
        bf16 h = __float2bfloat16(v);
        size_t o = (size_t)(n0 + ty + i) * K + k0 + tx;
        Th[o] = h;
        Tl[o] = __float2bfloat16(v - __bfloat162float(h));
    }
}

__global__ void __launch_bounds__(256) k_split_kernel()
{
    for (int i = blockIdx.x * 256 + threadIdx.x; i < 4194304; i += gridDim.x * 256) {
        float x = g_K[i];
        bf16 hv = __float2bfloat16(x);
        g_Kbh[i] = hv;
        g_Kbl[i] = __float2bfloat16(x - __bfloat162float(hv));
    }
}

__global__ void __launch_bounds__(256) v_transpose_kernel()
{
    __shared__ float ts[64][65];
    const int t0 = blockIdx.x * 64;
    const int bh = blockIdx.y;
    const float* Vg = g_V + ((size_t)bh * 1024 + t0) * 64;
    const int tid = threadIdx.x;
    #pragma unroll
    for (int q = 0; q < 4; q++) {
        int idx = tid + q * 256;
        int row = idx >> 4, c4 = (idx & 15) * 4;
        float4 v = *(const float4*)(Vg + (size_t)row * 64 + c4);
        ts[row][c4+0] = v.x; ts[row][c4+1] = v.y; ts[row][c4+2] = v.z; ts[row][c4+3] = v.w;
    }
    __syncthreads();
    #pragma unroll
    for (int q = 0; q < 4; q++) {
        int idx = tid + q * 256;
        int d = idx >> 4, t4 = (idx & 15) * 4;
        float v0 = ts[t4+0][d], v1 = ts[t4+1][d], v2 = ts[t4+2][d], v3 = ts[t4+3][d];
        uint32_t h0, l0, h1, l1;
        split2(v0, v1, h0, l0);
        split2(v2, v3, h1, l1);
        size_t dst = (size_t)bh * 65536 + (size_t)d * 1024 + t0 + t4;
        *(uint32_t*)&g_Vth[dst]     = h0;
        *(uint32_t*)&g_Vth[dst + 2] = h1;
        *(uint32_t*)&g_Vtl[dst]     = l0;
        *(uint32_t*)&g_Vtl[dst + 2] = l1;
    }
}

// ---------------------------------------------------------------------------
// bf16 3-product WMMA GEMM. R10 mainloop untouched.
// R14/15: accumulators initialized from a bias smem tile (bias add for free),
// epilogue is direct wmma::store_matrix_sync to global (no staging/scatter).
// ---------------------------------------------------------------------------
#define LDH 40
#define MATH_ (128*LDH)
#define MATB (MATH_*2)
#define STGB (4*MATB)
#define BIAS_OFF (2*STGB)                 // 81920
#define SMEM_GEMM (2*STGB + 16*132*4)     // 90368

__device__ __forceinline__ void ld_mat(uint32_t dstbase, const bf16* __restrict__ src,
                                       int r0, int k0, int K, int tid)
{
    #pragma unroll
    for (int j = 0; j < 2; j++) {
        int idx = tid + j * 256;
        int row = idx >> 2, c = idx & 3;
        cp16(dstbase + row * 80 + c * 16, src + (size_t)(r0 + row) * K + k0 + c * 8);
    }
}

#define LOADSTAGE(t_, s_) do {                                         \
    uint32_t b_ = sb + (s_) * STGB;                                    \
    ld_mat(b_,            Ah, m0, (t_) * 32, K, tid);                  \
    ld_mat(b_ +     MATB, Al, m0, (t_) * 32, K, tid);                  \
    ld_mat(b_ + 2 * MATB, Bh, n0, (t_) * 32, K, tid);                  \
    ld_mat(b_ + 3 * MATB, Bl, n0, (t_) * 32, K, tid);                  \
    asm volatile("cp.async.commit_group;" ::: "memory");               \
} while (0)

__global__ void __launch_bounds__(256, 2) gemm_bf16_kernel(
    int sel, const float* __restrict__ bias, float* __restrict__ Cout,
    int K, int mode, int ldc)
{
    extern __shared__ __align__(128) char smraw[];
    bf16* sh = (bf16*)smraw;
    float* Bsm = (float*)(smraw + BIAS_OFF);   // [16][132] bias tile
    uint32_t sb = smem_u32(smraw);

    const bf16* Ah = (sel == 0) ? g_xhi : g_Yhi;
    const bf16* Al = (sel == 0) ? g_xlo : g_Ylo;
    const bf16* Bh = (sel == 0) ? g_Wah : g_Wph;
    const bf16* Bl = (sel == 0) ? g_Wal : g_Wpl;

    const int tid = threadIdx.x, wid = tid >> 5;
    const int warp_m = wid & 1, warp_n = wid >> 1;
    const int m0 = blockIdx.y * 128;
    const int n0 = blockIdx.x * 128;
    const int NT = K >> 5;

    // start first stage load, then build bias tile while it's in flight
    LOADSTAGE(0, 0);
    for (int e = tid; e < 16 * 128; e += 256) {
        int row = e >> 7, col = e & 127;
        Bsm[row * 132 + col] = bias[n0 + col];
    }
    __syncthreads();

    wmma::fragment<wmma::accumulator, 16, 16, 16, float> facc[4][2];
    #pragma unroll
    for (int mi = 0; mi < 4; mi++)
        #pragma unroll
        for (int ni = 0; ni < 2; ni++)
            wmma::load_matrix_sync(facc[mi][ni], Bsm + warp_n * 32 + ni * 16, 132,
                                   wmma::mem_row_major);

    for (int t = 0; t < NT; t++) {
        if (t + 1 < NT) {
            LOADSTAGE(t + 1, (t + 1) & 1);
            asm volatile("cp.async.wait_group 1;" ::: "memory");
        } else {
            asm volatile("cp.async.wait_group 0;" ::: "memory");
        }
        __syncthreads();

        const bf16* Ahs = sh + (size_t)(t & 1) * (4 * MATH_);
        const bf16* Als = Ahs + MATH_;
        const bf16* Bhs = Ahs + 2 * MATH_;
        const bf16* Bls = Ahs + 3 * MATH_;

        #pragma unroll
        for (int kt = 0; kt < 32; kt += 16) {
            wmma::fragment<wmma::matrix_b, 16, 16, 16, bf16, wmma::col_major> fbh[2], fbl[2];
            #pragma unroll
            for (int ni = 0; ni < 2; ni++) {
                int nrow = warp_n * 32 + ni * 16;
                wmma::load_matrix_sync(fbh[ni], Bhs + nrow * LDH + kt, LDH);
                wmma::load_matrix_sync(fbl[ni], Bls + nrow * LDH + kt, LDH);
            }
            #pragma unroll
            for (int mi = 0; mi < 4; mi++) {
                wmma::fragment<wmma::matrix_a, 16, 16, 16, bf16, wmma::row_major> fah, fal;
                int mrow = warp_m * 64 + mi * 16;
                wmma::load_matrix_sync(fah, Ahs + mrow * LDH + kt, LDH);
                wmma::load_matrix_sync(fal, Als + mrow * LDH + kt, LDH);
                #pragma unroll
                for (int ni = 0; ni < 2; ni++) {
                    wmma::mma_sync(facc[mi][ni], fah, fbh[ni], facc[mi][ni]);
                    wmma::mma_sync(facc[mi][ni], fah, fbl[ni], facc[mi][ni]);
                    wmma::mma_sync(facc[mi][ni], fal, fbh[ni], facc[mi][ni]);
                }
            }
        }
        __syncthreads();
    }

    // epilogue: direct fragment stores to global
    if (mode == 1) {
        #pragma unroll
        for (int mi = 0; mi < 4; mi++) {
            int m = m0 + warp_m * 64 + mi * 16;
            #pragma unroll
            for (int ni = 0; ni < 2; ni++) {
                int n = n0 + warp_n * 32 + ni * 16;
                wmma::store_matrix_sync(Cout + (size_t)m * ldc + n, facc[mi][ni], ldc,
                                        wmma::mem_row_major);
            }
        }
    } else {
        // each 16x16 tile lives in one (which, bb, h) cell; dst stride 64
        const int which = n0 >> 10;
        float* base = (which == 0) ? g_Q : ((which == 1) ? g_K : g_V);
        const int cc0 = n0 & 1023;
        #pragma unroll
        for (int mi = 0; mi < 4; mi++) {
            int m = m0 + warp_m * 64 + mi * 16;
            int bb = m >> 10, tt = m & 1023;
            #pragma unroll
            for (int ni = 0; ni < 2; ni++) {
                int cc = cc0 + warp_n * 32 + ni * 16;
                int h = cc >> 6, d = cc & 63;
                float* dst = base + (size_t)(((bb * 16 + h) << 10) + tt) * 64 + d;
                wmma::store_matrix_sync(dst, facc[mi][ni], 64, wmma::mem_row_major);
            }
        }
    }
}

// ---------------------------------------------------------------------------
// pos table via wmma 3-product, OUTPUT LAYOUT [bh][i][j], bf16 storage.
// ---------------------------------------------------------------------------
#define POS_SMEM (4*9216 + 64*68*4)

__global__ void __launch_bounds__(256) pos_kernel()
{
    extern __shared__ __align__(16) char smraw[];
    bf16* Kh = (bf16*)(smraw);
    bf16* Kl = (bf16*)(smraw + 9216);
    bf16* Eh = (bf16*)(smraw + 18432);
    bf16* El = (bf16*)(smraw + 27648);
    float* Ssm = (float*)(smraw + 36864);   // [64][68]

    const int j0 = blockIdx.x * 64;
    const int r0 = blockIdx.y * 64;
    if (j0 + r0 >= Tdim) return;
    const int bh = blockIdx.z, h = bh & 15;
    const int tid = threadIdx.x, wid = tid >> 5;
    const int wm = wid & 3, wn = wid >> 2;
    const int lane = tid & 31;

    {
        const size_t kb = ((size_t)bh * Tdim + j0) * 64;
        const size_t eb = ((size_t)h * Tdim + r0) * 64;
        #pragma unroll
        for (int q = 0; q < 2; q++) {
            int idx = tid + q * 256;
            int row = idx >> 3, ch = (idx & 7) * 8;
            *(uint4*)(Kh + row * 72 + ch) = *(const uint4*)(g_Kbh + kb + row * 64 + ch);
            *(uint4*)(Kl + row * 72 + ch) = *(const uint4*)(g_Kbl + kb + row * 64 + ch);
            *(uint4*)(Eh + row * 72 + ch) = *(const uint4*)(g_Eh + eb + row * 64 + ch);
            *(uint4*)(El + row * 72 + ch) = *(const uint4*)(g_El + eb + row * 64 + ch);
        }
    }
    __syncthreads();

    wmma::fragment<wmma::accumulator, 16, 16, 16, float> acc[2];
    #pragma unroll
    for (int ni = 0; ni < 2; ni++) wmma::fill_fragment(acc[ni], 0.0f);
    #pragma unroll
    for (int k = 0; k < 4; k++) {
        wmma::fragment<wmma::matrix_a, 16, 16, 16, bf16, wmma::row_major> fah, fal;
        wmma::load_matrix_sync(fah, Kh + (wm * 16) * 72 + k * 16, 72);
        wmma::load_matrix_sync(fal, Kl + (wm * 16) * 72 + k * 16, 72);
        #pragma unroll
        for (int ni = 0; ni < 2; ni++) {
            wmma::fragment<wmma::matrix_b, 16, 16, 16, bf16, wmma::col_major> fbh, fbl;
            wmma::load_matrix_sync(fbh, Eh + (wn * 32 + ni * 16) * 72 + k * 16, 72);
            wmma::load_matrix_sync(fbl, El + (wn * 32 + ni * 16) * 72 + k * 16, 72);
            wmma::mma_sync(acc[ni], fah, fbh, acc[ni]);
            wmma::mma_sync(acc[ni], fah, fbl, acc[ni]);
            wmma::mma_sync(acc[ni], fal, fbh, acc[ni]);
        }
    }
    #pragma unroll
    for (int ni = 0; ni < 2; ni++)
        wmma::store_matrix_sync(Ssm + (wm * 16) * 68 + wn * 32 + ni * 16, acc[ni], 68,
                                wmma::mem_row_major);
    __syncthreads();

    bf16* Pb = g_P + ((size_t)bh << 20);
    for (int il = wid; il < 127; il += 8) {
        int i = j0 + r0 + il;
        if (i >= Tdim) break;
        #pragma unroll
        for (int hf = 0; hf < 2; hf++) {
            int jc = lane + hf * 32;
            int r = il - jc;
            if (r >= 0 && r < 64)
                Pb[(size_t)i * Tdim + j0 + jc] = __float2bfloat16(Ssm[jc * 68 + r]);
        }
    }
}

// ---------------------------------------------------------------------------
// FA2-style flash attention (raw mma), pre-split bf16 operands, cp.async x2.
// ---------------------------------------------------------------------------
#define FLD 72
#define FST_B 36864
#define FL_SMEM (2*FST_B)

#define FLASH_LOAD(jt_, s_) do {                                               \
    size_t kbase_ = ((size_t)bh * 1024 + (size_t)(jt_) * 64) * 64;             \
    size_t vbase_ = (size_t)bh * 65536 + (size_t)(jt_) * 64;                   \
    _Pragma("unroll")                                                          \
    for (int q_ = 0; q_ < 8; q_++) {                                           \
        int idx_ = tid + q_ * 256;                                             \
        int mat_ = idx_ >> 9, rem_ = idx_ & 511;                               \
        int row_ = rem_ >> 3, c_ = rem_ & 7;                                   \
        const bf16* src_;                                                      \
        if (mat_ == 0)      src_ = g_Kbh + kbase_ + row_ * 64 + c_ * 8;        \
        else if (mat_ == 1) src_ = g_Kbl + kbase_ + row_ * 64 + c_ * 8;        \
        else if (mat_ == 2) src_ = g_Vth + vbase_ + (size_t)row_ * 1024 + c_ * 8; \
        else                src_ = g_Vtl + vbase_ + (size_t)row_ * 1024 + c_ * 8; \
        cp16(sb + (s_) * FST_B + mat_ * 9216 + row_ * 144 + c_ * 16, src_);    \
    }                                                                          \
    asm volatile("cp.async.commit_group;" ::: "memory");                       \
} while (0)

__global__ void __launch_bounds__(256) flash_kernel()
{
    extern __shared__ __align__(16) char fsm[];
    uint16_t* SMh = (uint16_t*)fsm;
    uint32_t sb = smem_u32(fsm);

    const int ib = (int)gridDim.x - 1 - (int)blockIdx.x;   // heavy CTAs first
    const int i0 = ib * 128;
    const int bh = blockIdx.y;
    const int b = bh >> 4, h = bh & 15;
    const int tid = threadIdx.x, wid = tid >> 5, lane = tid & 31;
    const int g = lane >> 2, tig = lane & 3;
    const int iW = i0 + wid * 16;
    const int rA = iW + g, rB = rA + 8;

    uint32_t qh[4][4], ql[4][4];
    {
        const float* Qg = g_Q + (size_t)bh * (Tdim * 64);
        #pragma unroll
        for (int kc = 0; kc < 4; kc++) {
            float2 v0 = *(const float2*)(Qg + (size_t)rA * 64 + kc * 16 + 2 * tig);
            float2 v1 = *(const float2*)(Qg + (size_t)rB * 64 + kc * 16 + 2 * tig);
            float2 v2 = *(const float2*)(Qg + (size_t)rA * 64 + kc * 16 + 2 * tig + 8);
            float2 v3 = *(const float2*)(Qg + (size_t)rB * 64 + kc * 16 + 2 * tig + 8);
            split2(v0.x * CSCALE, v0.y * CSCALE, qh[kc][0], ql[kc][0]);
            split2(v1.x * CSCALE, v1.y * CSCALE, qh[kc][1], ql[kc][1]);
            split2(v2.x * CSCALE, v2.y * CSCALE, qh[kc][2], ql[kc][2]);
            split2(v3.x * CSCALE, v3.y * CSCALE, qh[kc][3], ql[kc][3]);
        }
    }

    float o[8][4];
    #pragma unroll
    for (int t = 0; t < 8; t++) { o[t][0] = 0.f; o[t][1] = 0.f; o[t][2] = 0.f; o[t][3] = 0.f; }
    float mA = -1e30f, mB = -1e30f, lA = 0.f, lB = 0.f;

    const bf16* Pb = g_P + ((size_t)bh << 20);
    const int njt = (i0 + 128) >> 6;

    FLASH_LOAD(0, 0);

    for (int jt = 0; jt < njt; jt++) {
        const int j0 = jt << 6;
        if (jt + 1 < njt) {
            FLASH_LOAD(jt + 1, (jt + 1) & 1);
            asm volatile("cp.async.wait_group 1;" ::: "memory");
        } else {
            asm volatile("cp.async.wait_group 0;" ::: "memory");
        }
        __syncthreads();

        if (j0 <= iW + 15) {
            const uint16_t* Khs = SMh + (jt & 1) * (FST_B / 2);
            const uint16_t* Kls = Khs + 4608;
            const uint16_t* Vhs = Khs + 9216;
            const uint16_t* Vls = Khs + 13824;

            float s[8][4];
            #pragma unroll
            for (int t = 0; t < 8; t++) {
                int j = j0 + t * 8 + 2 * tig;
                __nv_bfloat162 b0 = *(const __nv_bfloat162*)(Pb + (size_t)rA * Tdim + j);
                __nv_bfloat162 b1 = *(const __nv_bfloat162*)(Pb + (size_t)rB * Tdim + j);
                s[t][0] = __bfloat162float(b0.x) * CSCALE;
                s[t][1] = __bfloat162float(b0.y) * CSCALE;
                s[t][2] = __bfloat162float(b1.x) * CSCALE;
                s[t][3] = __bfloat162float(b1.y) * CSCALE;
            }
            #pragma unroll
            for (int kc = 0; kc < 4; kc++) {
                #pragma unroll
                for (int t = 0; t < 8; t++) {
                    uint32_t kb0 = *(const uint32_t*)&Khs[(t * 8 + g) * FLD + kc * 16 + 2 * tig];
                    uint32_t kb1 = *(const uint32_t*)&Khs[(t * 8 + g) * FLD + kc * 16 + 2 * tig + 8];
                    uint32_t kl0 = *(const uint32_t*)&Kls[(t * 8 + g) * FLD + kc * 16 + 2 * tig];
                    uint32_t kl1 = *(const uint32_t*)&Kls[(t * 8 + g) * FLD + kc * 16 + 2 * tig + 8];
                    mma16816(s[t], qh[kc][0], qh[kc][1], qh[kc][2], qh[kc][3], kb0, kb1);
                    mma16816(s[t], qh[kc][0], qh[kc][1], qh[kc][2], qh[kc][3], kl0, kl1);
                    mma16816(s[t], ql[kc][0], ql[kc][1], ql[kc][2], ql[kc][3], kb0, kb1);
                }
            }

            if (j0 + 63 > iW) {
                #pragma unroll
                for (int t = 0; t < 8; t++) {
                    int j = j0 + t * 8 + 2 * tig;
                    if (j     > rA) s[t][0] = -3e38f;
                    if (j + 1 > rA) s[t][1] = -3e38f;
                    if (j     > rB) s[t][2] = -3e38f;
                    if (j + 1 > rB) s[t][3] = -3e38f;
                }
            }

            float mxA = -3e38f, mxB = -3e38f;
            #pragma unroll
            for (int t = 0; t < 8; t++) {
                mxA = fmaxf(mxA, fmaxf(s[t][0], s[t][1]));
                mxB = fmaxf(mxB, fmaxf(s[t][2], s[t][3]));
            }
            mxA = fmaxf(mxA, __shfl_xor_sync(0xffffffffu, mxA, 1));
            mxA = fmaxf(mxA, __shfl_xor_sync(0xffffffffu, mxA, 2));
            mxB = fmaxf(mxB, __shfl_xor_sync(0xffffffffu, mxB, 1));
            mxB = fmaxf(mxB, __shfl_xor_sync(0xffffffffu, mxB, 2));
            float nmA = fmaxf(mA, mxA), nmB = fmaxf(mB, mxB);
            float cA = ex2f(mA - nmA), cB = ex2f(mB - nmB);
            mA = nmA; mB = nmB;
            float sumA = 0.f, sumB = 0.f;
            #pragma unroll
            for (int t = 0; t < 8; t++) {
                s[t][0] = ex2f(s[t][0] - nmA); sumA += s[t][0];
                s[t][1] = ex2f(s[t][1] - nmA); sumA += s[t][1];
                s[t][2] = ex2f(s[t][2] - nmB); sumB += s[t][2];
                s[t][3] = ex2f(s[t][3] - nmB); sumB += s[t][3];
            }
            sumA += __shfl_xor_sync(0xffffffffu, sumA, 1);
            sumA += __shfl_xor_sync(0xffffffffu, sumA, 2);
            sumB += __shfl_xor_sync(0xffffffffu, sumB, 1);
            sumB += __shfl_xor_sync(0xffffffffu, sumB, 2);
            lA = lA * cA + sumA; lB = lB * cB + sumB;
            #pragma unroll
            for (int t = 0; t < 8; t++) {
                o[t][0] *= cA; o[t][1] *= cA; o[t][2] *= cB; o[t][3] *= cB;
            }

            #pragma unroll
            for (int kc = 0; kc < 4; kc++) {
                uint32_t ah[4], al[4];
                split2(s[2*kc][0],   s[2*kc][1],   ah[0], al[0]);
                split2(s[2*kc][2],   s[2*kc][3],   ah[1], al[1]);
                split2(s[2*kc+1][0], s[2*kc+1][1], ah[2], al[2]);
                split2(s[2*kc+1][2], s[2*kc+1][3], ah[3], al[3]);
                #pragma unroll
                for (int t = 0; t < 8; t++) {
                    uint32_t vb0 = *(const uint32_t*)&Vhs[(t * 8 + g) * FLD + kc * 16 + 2 * tig];
                    uint32_t vb1 = *(const uint32_t*)&Vhs[(t * 8 + g) * FLD + kc * 16 + 2 * tig + 8];
                    uint32_t vl0 = *(const uint32_t*)&Vls[(t * 8 + g) * FLD + kc * 16 + 2 * tig];
                    uint32_t vl1 = *(const uint32_t*)&Vls[(t * 8 + g) * FLD + kc * 16 + 2 * tig + 8];
                    mma16816(o[t], ah[0], ah[1], ah[2], ah[3], vb0, vb1);
                    mma16816(o[t], ah[0], ah[1], ah[2], ah[3], vl0, vl1);
                    mma16816(o[t], al[0], al[1], al[2], al[3], vb0, vb1);
                }
            }
        }
        __syncthreads();
    }

    float iA = 1.f / lA, iB = 1.f / lB;
    size_t baseA = ((size_t)(b * Tdim + rA)) * 1024 + h * 64;
    size_t baseB = ((size_t)(b * Tdim + rB)) * 1024 + h * 64;
    #pragma unroll
    for (int t = 0; t < 8; t++) {
        int d = t * 8 + 2 * tig;
        uint32_t hi, lo;
        split2(o[t][0] * iA, o[t][1] * iA, hi, lo);
        *(uint32_t*)&g_Yhi[baseA + d] = hi;
        *(uint32_t*)&g_Ylo[baseA + d] = lo;
        split2(o[t][2] * iB, o[t][3] * iB, hi, lo);
        *(uint32_t*)&g_Yhi[baseB + d] = hi;
        *(uint32_t*)&g_Ylo[baseB + d] = lo;
    }
}

// ---------------------------------------------------------------------------
extern "C" void kernel_launch(void* const* d_in, const int* in_sizes, int n_in,
                              void* d_out, int out_size)
{
    const float* x      = (const float*)d_in[0];
    const float* W_attn = (const float*)d_in[1];
    const float* b_attn = (const float*)d_in[2];
    const float* W_proj = (const float*)d_in[3];
    const float* b_proj = (const float*)d_in[4];
    const float* rel    = (const float*)d_in[5];
    float* out = (float*)d_out;

    cudaFuncSetAttribute(gemm_bf16_kernel,
                         cudaFuncAttributeMaxDynamicSharedMemorySize, SMEM_GEMM);
    cudaFuncSetAttribute(pos_kernel,
                         cudaFuncAttributeMaxDynamicSharedMemorySize, POS_SMEM);
    cudaFuncSetAttribute(flash_kernel,
                         cudaFuncAttributeMaxDynamicSharedMemorySize, FL_SMEM);

    // prep
    split_kernel<<<2048, 256>>>(x, 4096 * 1024);
    rel_split_kernel<<<512, 256>>>(rel);
    transpose_split_kernel<<<dim3(3072/32, 1024/32), 256>>>(W_attn, 0, 1024, 3072);
    transpose_split_kernel<<<dim3(1024/32, 1024/32), 256>>>(W_proj, 1, 1024, 1024);

    // 1) QKV (wmma x3) -> f32 Q/K/V, bias-init accumulators + direct stores
    gemm_bf16_kernel<<<dim3(24, 32), 256, SMEM_GEMM>>>(0, b_attn, nullptr, 1024, 0, 0);

    // 1b) pre-split K (hi/lo) and V (hi/lo transposed) for flash
    k_split_kernel<<<2048, 256>>>();
    v_transpose_kernel<<<dim3(16, 64), 256>>>();

    // 2) relative-position table (wmma x3), [bh][i][j] layout, bf16, pre-split E
    pos_kernel<<<dim3(16, 16, 64), 256, POS_SMEM>>>();

    // 3) FA2 raw-mma flash with cp.async double buffering -> Yhi/Ylo
    flash_kernel<<<dim3(8, 64), 256, FL_SMEM>>>();

    // 4) out = Y @ W_proj + b_proj (wmma x3)
    gemm_bf16_kernel<<<dim3(8, 32), 256, SMEM_GEMM>>>(1, b_proj, out, 1024, 1, 1024);
}

// round 16
// speedup vs baseline: 1.0651x; 1.0065x over previous
#include <cuda_runtime.h>
#include <cuda_bf16.h>
#include <mma.h>
#include <cstdint>
#include <math.h>

using namespace nvcuda;
typedef __nv_bfloat16 bf16;

#define Tdim 1024
#define CSCALE 0.18033688011112f   /* 0.125 * log2(e) */

// Scratch (allocation-free __device__ globals; NEVER passed from host as args)
__device__ float g_Q[4194304];            // 16MB [bh][t][d] f32
__device__ float g_K[4194304];
__device__ float g_V[4194304];
__device__ bf16 g_P[67108864];            // 128MB [bh][i][j] bf16
__device__ bf16 g_xhi[4194304], g_xlo[4194304];
__device__ bf16 g_Wah[3145728], g_Wal[3145728];
__device__ bf16 g_Wph[1048576], g_Wpl[1048576];
__device__ bf16 g_Yhi[4194304], g_Ylo[4194304];
__device__ bf16 g_Eh[1048576], g_El[1048576];     // rel pre-split [h][r][d]
// pre-split attention operands
__device__ bf16 g_Kbh[4194304], g_Kbl[4194304];   // K hi/lo [bh][t][d]
__device__ bf16 g_Vth[4194304], g_Vtl[4194304];   // V hi/lo TRANSPOSED [bh][d][t]

// ---------------------------------------------------------------------------
__device__ __forceinline__ uint32_t smem_u32(const void* p) {
    uint32_t a;
    asm("{ .reg .u64 t; cvta.to.shared.u64 t, %1; cvt.u32.u64 %0, t; }" : "=r"(a) : "l"(p));
    return a;
}
__device__ __forceinline__ void cp16(uint32_t dst, const void* src) {
    asm volatile("cp.async.cg.shared.global [%0], [%1], 16;" :: "r"(dst), "l"(src) : "memory");
}
__device__ __forceinline__ float ex2f(float x) {
    float r; asm("ex2.approx.ftz.f32 %0, %1;" : "=f"(r) : "f"(x)); return r;
}
__device__ __forceinline__ void mma16816(float* c, uint32_t a0, uint32_t a1, uint32_t a2,
                                         uint32_t a3, uint32_t b0, uint32_t b1) {
    asm volatile("mma.sync.aligned.m16n8k16.row.col.f32.bf16.bf16.f32 "
        "{%0,%1,%2,%3}, {%4,%5,%6,%7}, {%8,%9}, {%0,%1,%2,%3};"
        : "+f"(c[0]), "+f"(c[1]), "+f"(c[2]), "+f"(c[3])
        : "r"(a0), "r"(a1), "r"(a2), "r"(a3), "r"(b0), "r"(b1));
}
__device__ __forceinline__ void split2(float x, float y, uint32_t& hi, uint32_t& lo) {
    bf16 hx = __float2bfloat16(x), hy = __float2bfloat16(y);
    hi = (uint32_t)__bfloat16_as_ushort(hx) | ((uint32_t)__bfloat16_as_ushort(hy) << 16);
    bf16 lx = __float2bfloat16(x - __bfloat162float(hx));
    bf16 ly = __float2bfloat16(y - __bfloat162float(hy));
    lo = (uint32_t)__bfloat16_as_ushort(lx) | ((uint32_t)__bfloat16_as_ushort(ly) << 16);
}

// ---------------------------------------------------------------------------
// prep kernels (R13 config)
// ---------------------------------------------------------------------------
__global__ void __launch_bounds__(256) split_kernel(const float* __restrict__ s, int n)
{
    for (int i = blockIdx.x * blockDim.x + threadIdx.x; i < n; i += gridDim.x * blockDim.x) {
        float x = s[i];
        bf16 h = __float2bfloat16(x);
        g_xhi[i] = h;
        g_xlo[i] = __float2bfloat16(x - __bfloat162float(h));
    }
}

__global__ void __launch_bounds__(256) rel_split_kernel(const float* __restrict__ rel)
{
    for (int i = blockIdx.x * blockDim.x + threadIdx.x; i < 1048576; i += gridDim.x * blockDim.x) {
        float x = rel[i];
        bf16 h = __float2bfloat16(x);
        g_Eh[i] = h;
        g_El[i] = __float2bfloat16(x - __bfloat162float(h));
    }
}

__global__ void __launch_bounds__(256) transpose_split_kernel(
    const float* __restrict__ W, int which, int K, int N)
{
    bf16* Th = (which == 0) ? g_Wah : g_Wph;
    bf16* Tl = (which == 0) ? g_Wal : g_Wpl;
    __shared__ float t[32][33];
    int n0 = blockIdx.x * 32, k0 = blockIdx.y * 32;
    int tx = threadIdx.x & 31, ty = threadIdx.x >> 5;
    #pragma unroll
    for (int i = 0; i < 32; i += 8)
        t[ty + i][tx] = W[(size_t)(k0 + ty + i) * N + n0 + tx];
    __syncthreads();
    #pragma unroll
    for (int i = 0; i < 32; i += 8) {
        float v = t[tx][ty + i];
        bf16 h = __float2bfloat16(v);
        size_t o = (size_t)(n0 + ty + i) * K + k0 + tx;
        Th[o] = h;
        Tl[o] = __float2bfloat16(v - __bfloat162float(h));
    }
}

__global__ void __launch_bounds__(256) k_split_kernel()
{
    for (int i = blockIdx.x * 256 + threadIdx.x; i < 4194304; i += gridDim.x * 256) {
        float x = g_K[i];
        bf16 hv = __float2bfloat16(x);
        g_Kbh[i] = hv;
        g_Kbl[i] = __float2bfloat16(x - __bfloat162float(hv));
    }
}

__global__ void __launch_bounds__(256) v_transpose_kernel()
{
    __shared__ float ts[64][65];
    const int t0 = blockIdx.x * 64;
    const int bh = blockIdx.y;
    const float* Vg = g_V + ((size_t)bh * 1024 + t0) * 64;
    const int tid = threadIdx.x;
    #pragma unroll
    for (int q = 0; q < 4; q++) {
        int idx = tid + q * 256;
        int row = idx >> 4, c4 = (idx & 15) * 4;
        float4 v = *(const float4*)(Vg + (size_t)row * 64 + c4);
        ts[row][c4+0] = v.x; ts[row][c4+1] = v.y; ts[row][c4+2] = v.z; ts[row][c4+3] = v.w;
    }
    __syncthreads();
    #pragma unroll
    for (int q = 0; q < 4; q++) {
        int idx = tid + q * 256;
        int d = idx >> 4, t4 = (idx & 15) * 4;
        float v0 = ts[t4+0][d], v1 = ts[t4+1][d], v2 = ts[t4+2][d], v3 = ts[t4+3][d];
        uint32_t h0, l0, h1, l1;
        split2(v0, v1, h0, l0);
        split2(v2, v3, h1, l1);
        size_t dst = (size_t)bh * 65536 + (size_t)d * 1024 + t0 + t4;
        *(uint32_t*)&g_Vth[dst]     = h0;
        *(uint32_t*)&g_Vth[dst + 2] = h1;
        *(uint32_t*)&g_Vtl[dst]     = l0;
        *(uint32_t*)&g_Vtl[dst + 2] = l1;
    }
}

// ---------------------------------------------------------------------------
// bf16 3-product WMMA GEMM (R15 config: bias-init accumulators, direct stores)
// ---------------------------------------------------------------------------
#define LDH 40
#define MATH_ (128*LDH)
#define MATB (MATH_*2)
#define STGB (4*MATB)
#define BIAS_OFF (2*STGB)                 // 81920
#define SMEM_GEMM (2*STGB + 16*132*4)     // 90368

__device__ __forceinline__ void ld_mat(uint32_t dstbase, const bf16* __restrict__ src,
                                       int r0, int k0, int K, int tid)
{
    #pragma unroll
    for (int j = 0; j < 2; j++) {
        int idx = tid + j * 256;
        int row = idx >> 2, c = idx & 3;
        cp16(dstbase + row * 80 + c * 16, src + (size_t)(r0 + row) * K + k0 + c * 8);
    }
}

#define LOADSTAGE(t_, s_) do {                                         \
    uint32_t b_ = sb + (s_) * STGB;                                    \
    ld_mat(b_,            Ah, m0, (t_) * 32, K, tid);                  \
    ld_mat(b_ +     MATB, Al, m0, (t_) * 32, K, tid);                  \
    ld_mat(b_ + 2 * MATB, Bh, n0, (t_) * 32, K, tid);                  \
    ld_mat(b_ + 3 * MATB, Bl, n0, (t_) * 32, K, tid);                  \
    asm volatile("cp.async.commit_group;" ::: "memory");               \
} while (0)

__global__ void __launch_bounds__(256, 2) gemm_bf16_kernel(
    int sel, const float* __restrict__ bias, float* __restrict__ Cout,
    int K, int mode, int ldc)
{
    extern __shared__ __align__(128) char smraw[];
    bf16* sh = (bf16*)smraw;
    float* Bsm = (float*)(smraw + BIAS_OFF);   // [16][132] bias tile
    uint32_t sb = smem_u32(smraw);

    const bf16* Ah = (sel == 0) ? g_xhi : g_Yhi;
    const bf16* Al = (sel == 0) ? g_xlo : g_Ylo;
    const bf16* Bh = (sel == 0) ? g_Wah : g_Wph;
    const bf16* Bl = (sel == 0) ? g_Wal : g_Wpl;

    const int tid = threadIdx.x, wid = tid >> 5;
    const int warp_m = wid & 1, warp_n = wid >> 1;
    const int m0 = blockIdx.y * 128;
    const int n0 = blockIdx.x * 128;
    const int NT = K >> 5;

    // start first stage load, then build bias tile while it's in flight
    LOADSTAGE(0, 0);
    for (int e = tid; e < 16 * 128; e += 256) {
        int row = e >> 7, col = e & 127;
        Bsm[row * 132 + col] = bias[n0 + col];
    }
    __syncthreads();

    wmma::fragment<wmma::accumulator, 16, 16, 16, float> facc[4][2];
    #pragma unroll
    for (int mi = 0; mi < 4; mi++)
        #pragma unroll
        for (int ni = 0; ni < 2; ni++)
            wmma::load_matrix_sync(facc[mi][ni], Bsm + warp_n * 32 + ni * 16, 132,
                                   wmma::mem_row_major);

    for (int t = 0; t < NT; t++) {
        if (t + 1 < NT) {
            LOADSTAGE(t + 1, (t + 1) & 1);
            asm volatile("cp.async.wait_group 1;" ::: "memory");
        } else {
            asm volatile("cp.async.wait_group 0;" ::: "memory");
        }
        __syncthreads();

        const bf16* Ahs = sh + (size_t)(t & 1) * (4 * MATH_);
        const bf16* Als = Ahs + MATH_;
        const bf16* Bhs = Ahs + 2 * MATH_;
        const bf16* Bls = Ahs + 3 * MATH_;

        #pragma unroll
        for (int kt = 0; kt < 32; kt += 16) {
            wmma::fragment<wmma::matrix_b, 16, 16, 16, bf16, wmma::col_major> fbh[2], fbl[2];
            #pragma unroll
            for (int ni = 0; ni < 2; ni++) {
                int nrow = warp_n * 32 + ni * 16;
                wmma::load_matrix_sync(fbh[ni], Bhs + nrow * LDH + kt, LDH);
                wmma::load_matrix_sync(fbl[ni], Bls + nrow * LDH + kt, LDH);
            }
            #pragma unroll
            for (int mi = 0; mi < 4; mi++) {
                wmma::fragment<wmma::matrix_a, 16, 16, 16, bf16, wmma::row_major> fah, fal;
                int mrow = warp_m * 64 + mi * 16;
                wmma::load_matrix_sync(fah, Ahs + mrow * LDH + kt, LDH);
                wmma::load_matrix_sync(fal, Als + mrow * LDH + kt, LDH);
                #pragma unroll
                for (int ni = 0; ni < 2; ni++) {
                    wmma::mma_sync(facc[mi][ni], fah, fbh[ni], facc[mi][ni]);
                    wmma::mma_sync(facc[mi][ni], fah, fbl[ni], facc[mi][ni]);
                    wmma::mma_sync(facc[mi][ni], fal, fbh[ni], facc[mi][ni]);
                }
            }
        }
        __syncthreads();
    }

    // epilogue: direct fragment stores to global
    if (mode == 1) {
        #pragma unroll
        for (int mi = 0; mi < 4; mi++) {
            int m = m0 + warp_m * 64 + mi * 16;
            #pragma unroll
            for (int ni = 0; ni < 2; ni++) {
                int n = n0 + warp_n * 32 + ni * 16;
                wmma::store_matrix_sync(Cout + (size_t)m * ldc + n, facc[mi][ni], ldc,
                                        wmma::mem_row_major);
            }
        }
    } else {
        // each 16x16 tile lives in one (which, bb, h) cell; dst stride 64
        const int which = n0 >> 10;
        float* base = (which == 0) ? g_Q : ((which == 1) ? g_K : g_V);
        const int cc0 = n0 & 1023;
        #pragma unroll
        for (int mi = 0; mi < 4; mi++) {
            int m = m0 + warp_m * 64 + mi * 16;
            int bb = m >> 10, tt = m & 1023;
            #pragma unroll
            for (int ni = 0; ni < 2; ni++) {
                int cc = cc0 + warp_n * 32 + ni * 16;
                int h = cc >> 6, d = cc & 63;
                float* dst = base + (size_t)(((bb * 16 + h) << 10) + tt) * 64 + d;
                wmma::store_matrix_sync(dst, facc[mi][ni], 64, wmma::mem_row_major);
            }
        }
    }
}

// ---------------------------------------------------------------------------
// pos table via wmma 3-product, OUTPUT LAYOUT [bh][i][j], bf16 storage.
// ---------------------------------------------------------------------------
#define POS_SMEM (4*9216 + 64*68*4)

__global__ void __launch_bounds__(256) pos_kernel()
{
    extern __shared__ __align__(16) char smraw[];
    bf16* Kh = (bf16*)(smraw);
    bf16* Kl = (bf16*)(smraw + 9216);
    bf16* Eh = (bf16*)(smraw + 18432);
    bf16* El = (bf16*)(smraw + 27648);
    float* Ssm = (float*)(smraw + 36864);   // [64][68]

    const int j0 = blockIdx.x * 64;
    const int r0 = blockIdx.y * 64;
    if (j0 + r0 >= Tdim) return;
    const int bh = blockIdx.z, h = bh & 15;
    const int tid = threadIdx.x, wid = tid >> 5;
    const int wm = wid & 3, wn = wid >> 2;
    const int lane = tid & 31;

    {
        const size_t kb = ((size_t)bh * Tdim + j0) * 64;
        const size_t eb = ((size_t)h * Tdim + r0) * 64;
        #pragma unroll
        for (int q = 0; q < 2; q++) {
            int idx = tid + q * 256;
            int row = idx >> 3, ch = (idx & 7) * 8;
            *(uint4*)(Kh + row * 72 + ch) = *(const uint4*)(g_Kbh + kb + row * 64 + ch);
            *(uint4*)(Kl + row * 72 + ch) = *(const uint4*)(g_Kbl + kb + row * 64 + ch);
            *(uint4*)(Eh + row * 72 + ch) = *(const uint4*)(g_Eh + eb + row * 64 + ch);
            *(uint4*)(El + row * 72 + ch) = *(const uint4*)(g_El + eb + row * 64 + ch);
        }
    }
    __syncthreads();

    wmma::fragment<wmma::accumulator, 16, 16, 16, float> acc[2];
    #pragma unroll
    for (int ni = 0; ni < 2; ni++) wmma::fill_fragment(acc[ni], 0.0f);
    #pragma unroll
    for (int k = 0; k < 4; k++) {
        wmma::fragment<wmma::matrix_a, 16, 16, 16, bf16, wmma::row_major> fah, fal;
        wmma::load_matrix_sync(fah, Kh + (wm * 16) * 72 + k * 16, 72);
        wmma::load_matrix_sync(fal, Kl + (wm * 16) * 72 + k * 16, 72);
        #pragma unroll
        for (int ni = 0; ni < 2; ni++) {
            wmma::fragment<wmma::matrix_b, 16, 16, 16, bf16, wmma::col_major> fbh, fbl;
            wmma::load_matrix_sync(fbh, Eh + (wn * 32 + ni * 16) * 72 + k * 16, 72);
            wmma::load_matrix_sync(fbl, El + (wn * 32 + ni * 16) * 72 + k * 16, 72);
            wmma::mma_sync(acc[ni], fah, fbh, acc[ni]);
            wmma::mma_sync(acc[ni], fah, fbl, acc[ni]);
            wmma::mma_sync(acc[ni], fal, fbh, acc[ni]);
        }
    }
    #pragma unroll
    for (int ni = 0; ni < 2; ni++)
        wmma::store_matrix_sync(Ssm + (wm * 16) * 68 + wn * 32 + ni * 16, acc[ni], 68,
                                wmma::mem_row_major);
    __syncthreads();

    bf16* Pb = g_P + ((size_t)bh << 20);
    for (int il = wid; il < 127; il += 8) {
        int i = j0 + r0 + il;
        if (i >= Tdim) break;
        #pragma unroll
        for (int hf = 0; hf < 2; hf++) {
            int jc = lane + hf * 32;
            int r = il - jc;
            if (r >= 0 && r < 64)
                Pb[(size_t)i * Tdim + j0 + jc] = __float2bfloat16(Ssm[jc * 68 + r]);
        }
    }
}

// ---------------------------------------------------------------------------
// FA2-style flash attention (raw mma), pre-split bf16 operands.
// R16: 4-stage cp.async ring, prefetch distance 2, ONE barrier per tile.
// Buffer (jt+2)%4 was last read at iter jt-2; all threads passed the barrier
// at top of jt-1 (which sequences after their jt-2 compute), so the load
// issued at top of jt cannot clobber live data. End-of-loop barrier removed.
// ---------------------------------------------------------------------------
#define FLD 72
#define FST_B 36864
#define FL_SMEM (4*FST_B)

#define FLASH_LOAD(jt_, s_) do {                                               \
    size_t kbase_ = ((size_t)bh * 1024 + (size_t)(jt_) * 64) * 64;             \
    size_t vbase_ = (size_t)bh * 65536 + (size_t)(jt_) * 64;                   \
    _Pragma("unroll")                                                          \
    for (int q_ = 0; q_ < 8; q_++) {                                           \
        int idx_ = tid + q_ * 256;                                             \
        int mat_ = idx_ >> 9, rem_ = idx_ & 511;                               \
        int row_ = rem_ >> 3, c_ = rem_ & 7;                                   \
        const bf16* src_;                                                      \
        if (mat_ == 0)      src_ = g_Kbh + kbase_ + row_ * 64 + c_ * 8;        \
        else if (mat_ == 1) src_ = g_Kbl + kbase_ + row_ * 64 + c_ * 8;        \
        else if (mat_ == 2) src_ = g_Vth + vbase_ + (size_t)row_ * 1024 + c_ * 8; \
        else                src_ = g_Vtl + vbase_ + (size_t)row_ * 1024 + c_ * 8; \
        cp16(sb + (s_) * FST_B + mat_ * 9216 + row_ * 144 + c_ * 16, src_);    \
    }                                                                          \
    asm volatile("cp.async.commit_group;" ::: "memory");                       \
} while (0)

__global__ void __launch_bounds__(256) flash_kernel()
{
    extern __shared__ __align__(16) char fsm[];
    uint16_t* SMh = (uint16_t*)fsm;
    uint32_t sb = smem_u32(fsm);

    const int ib = (int)gridDim.x - 1 - (int)blockIdx.x;   // heavy CTAs first
    const int i0 = ib * 128;
    const int bh = blockIdx.y;
    const int b = bh >> 4, h = bh & 15;
    const int tid = threadIdx.x, wid = tid >> 5, lane = tid & 31;
    const int g = lane >> 2, tig = lane & 3;
    const int iW = i0 + wid * 16;
    const int rA = iW + g, rB = rA + 8;

    uint32_t qh[4][4], ql[4][4];
    {
        const float* Qg = g_Q + (size_t)bh * (Tdim * 64);
        #pragma unroll
        for (int kc = 0; kc < 4; kc++) {
            float2 v0 = *(const float2*)(Qg + (size_t)rA * 64 + kc * 16 + 2 * tig);
            float2 v1 = *(const float2*)(Qg + (size_t)rB * 64 + kc * 16 + 2 * tig);
            float2 v2 = *(const float2*)(Qg + (size_t)rA * 64 + kc * 16 + 2 * tig + 8);
            float2 v3 = *(const float2*)(Qg + (size_t)rB * 64 + kc * 16 + 2 * tig + 8);
            split2(v0.x * CSCALE, v0.y * CSCALE, qh[kc][0], ql[kc][0]);
            split2(v1.x * CSCALE, v1.y * CSCALE, qh[kc][1], ql[kc][1]);
            split2(v2.x * CSCALE, v2.y * CSCALE, qh[kc][2], ql[kc][2]);
            split2(v3.x * CSCALE, v3.y * CSCALE, qh[kc][3], ql[kc][3]);
        }
    }

    float o[8][4];
    #pragma unroll
    for (int t = 0; t < 8; t++) { o[t][0] = 0.f; o[t][1] = 0.f; o[t][2] = 0.f; o[t][3] = 0.f; }
    float mA = -1e30f, mB = -1e30f, lA = 0.f, lB = 0.f;

    const bf16* Pb = g_P + ((size_t)bh << 20);
    const int njt = (i0 + 128) >> 6;   // always >= 2

    FLASH_LOAD(0, 0);
    FLASH_LOAD(1, 1);

    for (int jt = 0; jt < njt; jt++) {
        const int j0 = jt << 6;
        if (jt + 2 < njt) {
            FLASH_LOAD(jt + 2, (jt + 2) & 3);
            asm volatile("cp.async.wait_group 2;" ::: "memory");
        } else if (jt + 1 < njt) {
            asm volatile("cp.async.wait_group 1;" ::: "memory");
        } else {
            asm volatile("cp.async.wait_group 0;" ::: "memory");
        }
        __syncthreads();   // single barrier per tile: cross-thread cp.async visibility

        if (j0 <= iW + 15) {
            const uint16_t* Khs = SMh + (jt & 3) * (FST_B / 2);
            const uint16_t* Kls = Khs + 4608;
            const uint16_t* Vhs = Khs + 9216;
            const uint16_t* Vls = Khs + 13824;

            float s[8][4];
            #pragma unroll
            for (int t = 0; t < 8; t++) {
                int j = j0 + t * 8 + 2 * tig;
                __nv_bfloat162 b0 = *(const __nv_bfloat162*)(Pb + (size_t)rA * Tdim + j);
                __nv_bfloat162 b1 = *(const __nv_bfloat162*)(Pb + (size_t)rB * Tdim + j);
                s[t][0] = __bfloat162float(b0.x) * CSCALE;
                s[t][1] = __bfloat162float(b0.y) * CSCALE;
                s[t][2] = __bfloat162float(b1.x) * CSCALE;
                s[t][3] = __bfloat162float(b1.y) * CSCALE;
            }
            #pragma unroll
            for (int kc = 0; kc < 4; kc++) {
                #pragma unroll
                for (int t = 0; t < 8; t++) {
                    uint32_t kb0 = *(const uint32_t*)&Khs[(t * 8 + g) * FLD + kc * 16 + 2 * tig];
                    uint32_t kb1 = *(const uint32_t*)&Khs[(t * 8 + g) * FLD + kc * 16 + 2 * tig + 8];
                    uint32_t kl0 = *(const uint32_t*)&Kls[(t * 8 + g) * FLD + kc * 16 + 2 * tig];
                    uint32_t kl1 = *(const uint32_t*)&Kls[(t * 8 + g) * FLD + kc * 16 + 2 * tig + 8];
                    mma16816(s[t], qh[kc][0], qh[kc][1], qh[kc][2], qh[kc][3], kb0, kb1);
                    mma16816(s[t], qh[kc][0], qh[kc][1], qh[kc][2], qh[kc][3], kl0, kl1);
                    mma16816(s[t], ql[kc][0], ql[kc][1], ql[kc][2], ql[kc][3], kb0, kb1);
                }
            }

            if (j0 + 63 > iW) {
                #pragma unroll
                for (int t = 0; t < 8; t++) {
                    int j = j0 + t * 8 + 2 * tig;
                    if (j     > rA) s[t][0] = -3e38f;
                    if (j + 1 > rA) s[t][1] = -3e38f;
                    if (j     > rB) s[t][2] = -3e38f;
                    if (j + 1 > rB) s[t][3] = -3e38f;
                }
            }

            float mxA = -3e38f, mxB = -3e38f;
            #pragma unroll
            for (int t = 0; t < 8; t++) {
                mxA = fmaxf(mxA, fmaxf(s[t][0], s[t][1]));
                mxB = fmaxf(mxB, fmaxf(s[t][2], s[t][3]));
            }
            mxA = fmaxf(mxA, __shfl_xor_sync(0xffffffffu, mxA, 1));
            mxA = fmaxf(mxA, __shfl_xor_sync(0xffffffffu, mxA, 2));
            mxB = fmaxf(mxB, __shfl_xor_sync(0xffffffffu, mxB, 1));
            mxB = fmaxf(mxB, __shfl_xor_sync(0xffffffffu, mxB, 2));
            float nmA = fmaxf(mA, mxA), nmB = fmaxf(mB, mxB);
            float cA = ex2f(mA - nmA), cB = ex2f(mB - nmB);
            mA = nmA; mB = nmB;
            float sumA = 0.f, sumB = 0.f;
            #pragma unroll
            for (int t = 0; t < 8; t++) {
                s[t][0] = ex2f(s[t][0] - nmA); sumA += s[t][0];
                s[t][1] = ex2f(s[t][1] - nmA); sumA += s[t][1];
                s[t][2] = ex2f(s[t][2] - nmB); sumB += s[t][2];
                s[t][3] = ex2f(s[t][3] - nmB); sumB += s[t][3];
            }
            sumA += __shfl_xor_sync(0xffffffffu, sumA, 1);
            sumA += __shfl_xor_sync(0xffffffffu, sumA, 2);
            sumB += __shfl_xor_sync(0xffffffffu, sumB, 1);
            sumB += __shfl_xor_sync(0xffffffffu, sumB, 2);
            lA = lA * cA + sumA; lB = lB * cB + sumB;
            #pragma unroll
            for (int t = 0; t < 8; t++) {
                o[t][0] *= cA; o[t][1] *= cA; o[t][2] *= cB; o[t][3] *= cB;
            }

            #pragma unroll
            for (int kc = 0; kc < 4; kc++) {
                uint32_t ah[4], al[4];
                split2(s[2*kc][0],   s[2*kc][1],   ah[0], al[0]);
                split2(s[2*kc][2],   s[2*kc][3],   ah[1], al[1]);
                split2(s[2*kc+1][0], s[2*kc+1][1], ah[2], al[2]);
                split2(s[2*kc+1][2], s[2*kc+1][3], ah[3], al[3]);
                #pragma unroll
                for (int t = 0; t < 8; t++) {
                    uint32_t vb0 = *(const uint32_t*)&Vhs[(t * 8 + g) * FLD + kc * 16 + 2 * tig];
                    uint32_t vb1 = *(const uint32_t*)&Vhs[(t * 8 + g) * FLD + kc * 16 + 2 * tig + 8];
                    uint32_t vl0 = *(const uint32_t*)&Vls[(t * 8 + g) * FLD + kc * 16 + 2 * tig];
                    uint32_t vl1 = *(const uint32_t*)&Vls[(t * 8 + g) * FLD + kc * 16 + 2 * tig + 8];
                    mma16816(o[t], ah[0], ah[1], ah[2], ah[3], vb0, vb1);
                    mma16816(o[t], ah[0], ah[1], ah[2], ah[3], vl0, vl1);
                    mma16816(o[t], al[0], al[1], al[2], al[3], vb0, vb1);
                }
            }
        }
    }

    float iA = 1.f / lA, iB = 1.f / lB;
    size_t baseA = ((size_t)(b * Tdim + rA)) * 1024 + h * 64;
    size_t baseB = ((size_t)(b * Tdim + rB)) * 1024 + h * 64;
    #pragma unroll
    for (int t = 0; t < 8; t++) {
        int d = t * 8 + 2 * tig;
        uint32_t hi, lo;
        split2(o[t][0] * iA, o[t][1] * iA, hi, lo);
        *(uint32_t*)&g_Yhi[baseA + d] = hi;
        *(uint32_t*)&g_Ylo[baseA + d] = lo;
        split2(o[t][2] * iB, o[t][3] * iB, hi, lo);
        *(uint32_t*)&g_Yhi[baseB + d] = hi;
        *(uint32_t*)&g_Ylo[baseB + d] = lo;
    }
}

// ---------------------------------------------------------------------------
extern "C" void kernel_launch(void* const* d_in, const int* in_sizes, int n_in,
                              void* d_out, int out_size)
{
    const float* x      = (const float*)d_in[0];
    const float* W_attn = (const float*)d_in[1];
    const float* b_attn = (const float*)d_in[2];
    const float* W_proj = (const float*)d_in[3];
    const float* b_proj = (const float*)d_in[4];
    const float* rel    = (const float*)d_in[5];
    float* out = (float*)d_out;

    cudaFuncSetAttribute(gemm_bf16_kernel,
                         cudaFuncAttributeMaxDynamicSharedMemorySize, SMEM_GEMM);
    cudaFuncSetAttribute(pos_kernel,
                         cudaFuncAttributeMaxDynamicSharedMemorySize, POS_SMEM);
    cudaFuncSetAttribute(flash_kernel,
                         cudaFuncAttributeMaxDynamicSharedMemorySize, FL_SMEM);

    // prep
    split_kernel<<<2048, 256>>>(x, 4096 * 1024);
    rel_split_kernel<<<512, 256>>>(rel);
    transpose_split_kernel<<<dim3(3072/32, 1024/32), 256>>>(W_attn, 0, 1024, 3072);
    transpose_split_kernel<<<dim3(1024/32, 1024/32), 256>>>(W_proj, 1, 1024, 1024);

    // 1) QKV (wmma x3) -> f32 Q/K/V, bias-init accumulators + direct stores
    gemm_bf16_kernel<<<dim3(24, 32), 256, SMEM_GEMM>>>(0, b_attn, nullptr, 1024, 0, 0);

    // 1b) pre-split K (hi/lo) and V (hi/lo transposed) for flash
    k_split_kernel<<<2048, 256>>>();
    v_transpose_kernel<<<dim3(16, 64), 256>>>();

    // 2) relative-position table (wmma x3), [bh][i][j] layout, bf16, pre-split E
    pos_kernel<<<dim3(16, 16, 64), 256, POS_SMEM>>>();

    // 3) FA2 raw-mma flash, 4-stage ring, one barrier per tile -> Yhi/Ylo
    flash_kernel<<<dim3(8, 64), 256, FL_SMEM>>>();

    // 4) out = Y @ W_proj + b_proj (wmma x3)
    gemm_bf16_kernel<<<dim3(8, 32), 256, SMEM_GEMM>>>(1, b_proj, out, 1024, 1, 1024);
}